// round 11
// baseline (speedup 1.0000x reference)
#include <cuda_runtime.h>
#include <cuda_bf16.h>
#include <cuda_fp16.h>
#include <cstdint>
#include <cstddef>

#define Bb   128
#define Tt   128
#define Cc   256
#define Hh   4
#define HSz  64
#define Ll   6
#define Vv   10000
#define DFFz 1024
#define MROWS (Bb*Tt)   // 16384
#define VPAD 10112      // ceil(10000/128)*128
#define QS   (3*Cc)     // fused qkv row stride (768)
#define K1   (2*Cc)     // 512  (fp16 2-term split)
#define K2   (2*DFFz)   // 2048

// ================= scratch (device globals) =================
__device__ __align__(256) float g_x  [MROWS * Cc];
__device__ __align__(256) float g_qkv[MROWS * QS];
__device__ __align__(256) __half g_act2[MROWS * K1];          // split acts [M, 512]
__device__ __align__(256) __half g_ff2 [MROWS * K2];          // split ff acts [M, 2048]
__device__ __align__(256) __half g_bqkv[Ll * QS   * K1];      // [768, 512] per layer
__device__ __align__(256) __half g_bp  [Ll * Cc   * K1];
__device__ __align__(256) __half g_bw1 [Ll * DFFz * K1];      // [1024, 512]
__device__ __align__(256) __half g_bw2 [Ll * Cc   * K2];      // [256, 2048]
__device__ __align__(256) __half g_blm [VPAD * K1];           // [10112, 512]

// ================= PTX helpers (arch-agnostic, valid on sm_103) =====
__device__ __forceinline__ uint32_t smem_u32(const void* p) {
    uint32_t a;
    asm("{ .reg .u64 t; cvta.to.shared.u64 t, %1; cvt.u32.u64 %0, t; }" : "=r"(a) : "l"(p));
    return a;
}
__device__ __forceinline__ void cp_async16(uint32_t saddr, const void* gaddr) {
    asm volatile("cp.async.cg.shared.global [%0], [%1], 16;" :: "r"(saddr), "l"(gaddr));
}
__device__ __forceinline__ void cp_commit() { asm volatile("cp.async.commit_group;" ::: "memory"); }
template <int N>
__device__ __forceinline__ void cp_wait() { asm volatile("cp.async.wait_group %0;" :: "n"(N) : "memory"); }

__device__ __forceinline__ void ldm_x4(uint32_t& r0, uint32_t& r1, uint32_t& r2, uint32_t& r3,
                                       uint32_t addr) {
    asm volatile("ldmatrix.sync.aligned.m8n8.x4.shared.b16 {%0,%1,%2,%3}, [%4];"
                 : "=r"(r0), "=r"(r1), "=r"(r2), "=r"(r3) : "r"(addr));
}
__device__ __forceinline__ void mma_f16(float* d, const uint32_t* a, const uint32_t* b) {
    asm volatile("mma.sync.aligned.m16n8k16.row.col.f32.f16.f16.f32 "
                 "{%0,%1,%2,%3}, {%4,%5,%6,%7}, {%8,%9}, {%0,%1,%2,%3};"
                 : "+f"(d[0]), "+f"(d[1]), "+f"(d[2]), "+f"(d[3])
                 : "r"(a[0]), "r"(a[1]), "r"(a[2]), "r"(a[3]), "r"(b[0]), "r"(b[1]));
}

// ================= embedding =================
__global__ void embed_kernel(const int* __restrict__ idx, const float* __restrict__ tok,
                             const float* __restrict__ pos, float* __restrict__ x) {
    int bt = blockIdx.x;
    int t  = bt % Tt;
    int tokid = idx[bt];
    int c = threadIdx.x;
    x[(size_t)bt * Cc + c] = tok[(size_t)tokid * Cc + c] + pos[(size_t)t * Cc + c];
}

// ================= layernorm -> fp16 2-term split [M, 512], 2 rows/block ========
__global__ void ln_split_kernel(const float* __restrict__ x, const float* __restrict__ gam,
                                const float* __restrict__ bet, __half* __restrict__ out2) {
    int row = blockIdx.x * 2 + threadIdx.y;
    int tid = threadIdx.x;          // 0..255
    float v = x[(size_t)row * Cc + tid];
    float s = v, sq = v * v;
    #pragma unroll
    for (int o = 16; o > 0; o >>= 1) {
        s  += __shfl_xor_sync(0xFFFFFFFFu, s,  o);
        sq += __shfl_xor_sync(0xFFFFFFFFu, sq, o);
    }
    __shared__ float ws[2][8], wsq[2][8];
    if ((tid & 31) == 0) { ws[threadIdx.y][tid >> 5] = s; wsq[threadIdx.y][tid >> 5] = sq; }
    __syncthreads();
    float S = 0.f, Q = 0.f;
    #pragma unroll
    for (int i = 0; i < 8; i++) { S += ws[threadIdx.y][i]; Q += wsq[threadIdx.y][i]; }
    float mean = S * (1.0f / Cc);
    float var  = Q * (1.0f / Cc) - mean * mean;
    float inv  = rsqrtf(var + 1e-5f);
    float y = (v - mean) * inv * gam[tid] + bet[tid];
    __half hi = __float2half(y);
    __half lo = __float2half(y - __half2float(hi));
    size_t o = (size_t)row * K1;
    out2[o + tid]      = hi;
    out2[o + Cc + tid] = lo;
}

// ================= weight transpose, fp16 duplicated: W[K,N] -> out[n, 2K] ======
__global__ void wsplit_f16_kernel(const float* __restrict__ W, __half* __restrict__ out,
                                  int K, int N, size_t lstride) {
    int l = blockIdx.z;
    W   += (size_t)l * K * N;
    out += (size_t)l * lstride;
    __shared__ float tile[32][33];
    int k0 = blockIdx.y * 32, n0 = blockIdx.x * 32;
    int tx = threadIdx.x, ty = threadIdx.y;   // 32 x 8
    #pragma unroll
    for (int i = 0; i < 32; i += 8) {
        int k = k0 + ty + i, n = n0 + tx;
        tile[ty + i][tx] = (n < N) ? W[(size_t)k * N + n] : 0.f;
    }
    __syncthreads();
    #pragma unroll
    for (int i = 0; i < 32; i += 8) {
        int n = n0 + ty + i, k = k0 + tx;
        __half h = __float2half(tile[tx][ty + i]);
        size_t rb = (size_t)n * 2 * K;
        out[rb + k]     = h;
        out[rb + K + k] = h;
    }
}

// ================= HMMA fp16 GEMM, templated tile/stages, 2 CTAs/SM =============
// D[M, N] = A2[M, Kfull] @ B2[N, Kfull]^T, fp32 accum. N-tile fixed 128, BK=64.
// MTILE=128: 8 warps 4Mx2N (warp 32x64), 3-stage. MTILE=64: 8 warps 2Mx4N (warp 32x32), 4-stage.
#define LDA 72
#define GEMM_SMEM 110592   // == 3*(128+128)*72*2 == 4*(64+128)*72*2

template <int MTILE, int NSTAGE>
__global__ void __launch_bounds__(256, 2)
gemm_tc(const __half* __restrict__ A2, const __half* __restrict__ B2,
        const float* __restrict__ bias, const float* __restrict__ Rres,
        float* __restrict__ D32, __half* __restrict__ D2,
        int Kfull, int N, int relu) {
    constexpr int WM   = (MTILE == 128) ? 4 : 2;   // M-warps
    constexpr int WN   = 8 / WM;                   // N-warps
    constexpr int WNT  = 128 / WN;                 // warp n-width (64 / 32)
    constexpr int NT   = WNT / 8;                  // 8x8 n-frags per warp (8 / 4)
    constexpr int AELE = MTILE * LDA;
    constexpr int STG  = (MTILE + 128) * LDA;      // elems per stage
    constexpr int ALD  = MTILE * 8 / 256;          // A vec-loads per thread (4 / 2)

    extern __shared__ char smem_raw[];
    uint32_t sb = smem_u32(smem_raw);
    int tid = threadIdx.x, lane = tid & 31, wid = tid >> 5;
    int wm = wid % WM, wn = wid / WM;
    int bx = blockIdx.x, by = blockIdx.y;

    const __half* Abase = A2 + (size_t)(by * MTILE) * Kfull;
    const __half* Bbase = B2 + (size_t)(bx * 128) * Kfull;
    int nch = Kfull >> 6;

    float acc[2][NT][4];
    #pragma unroll
    for (int mt = 0; mt < 2; mt++)
        #pragma unroll
        for (int nt = 0; nt < NT; nt++)
            #pragma unroll
            for (int i = 0; i < 4; i++) acc[mt][nt][i] = 0.f;

    auto issue_load = [&](int kc, int buf) {
        const __half* Ag = Abase + kc * 64;
        const __half* Bg = Bbase + kc * 64;
        uint32_t sA = sb + (uint32_t)(buf * STG) * 2;
        uint32_t sB = sA + (uint32_t)AELE * 2;
        #pragma unroll
        for (int j = 0; j < ALD; j++) {
            int lin = tid + j * 256;
            int r = lin >> 3, u = (lin & 7) << 3;
            cp_async16(sA + (uint32_t)(r * LDA + u) * 2, Ag + (size_t)r * Kfull + u);
        }
        #pragma unroll
        for (int j = 0; j < 4; j++) {
            int lin = tid + j * 256;
            int r = lin >> 3, u = (lin & 7) << 3;
            cp_async16(sB + (uint32_t)(r * LDA + u) * 2, Bg + (size_t)r * Kfull + u);
        }
        cp_commit();
    };

    #pragma unroll
    for (int s = 0; s < NSTAGE - 1; s++)
        if (s < nch) issue_load(s, s);

    int a_row = wm * 32 + (lane & 15);
    int a_kc  = (lane >> 4) * 8;
    int b_row = wn * WNT + (lane & 7) + ((lane >> 4) << 3);
    int b_kc  = (lane & 8);

    for (int kc = 0; kc < nch; kc++) {
        if      (kc + NSTAGE - 2 < nch && NSTAGE >= 4) cp_wait<(NSTAGE >= 4) ? NSTAGE - 2 : 0>();
        else if (kc + 1 < nch)                          cp_wait<1>();
        else                                            cp_wait<0>();
        __syncthreads();           // orders prior-buffer reads before reissue below
        if (kc + NSTAGE - 1 < nch) issue_load(kc + NSTAGE - 1, (kc + NSTAGE - 1) % NSTAGE);

        int buf = kc % NSTAGE;
        uint32_t sA = sb + (uint32_t)(buf * STG) * 2;
        uint32_t sB = sA + (uint32_t)AELE * 2;

        #pragma unroll
        for (int ks = 0; ks < 4; ks++) {
            uint32_t a[2][4], b[NT][2];
            #pragma unroll
            for (int mt = 0; mt < 2; mt++) {
                uint32_t addr = sA + (uint32_t)((a_row + mt * 16) * LDA + ks * 16 + a_kc) * 2;
                ldm_x4(a[mt][0], a[mt][1], a[mt][2], a[mt][3], addr);
            }
            #pragma unroll
            for (int ntp = 0; ntp < NT / 2; ntp++) {
                uint32_t addr = sB + (uint32_t)((b_row + ntp * 16) * LDA + ks * 16 + b_kc) * 2;
                ldm_x4(b[ntp*2][0], b[ntp*2][1], b[ntp*2+1][0], b[ntp*2+1][1], addr);
            }
            #pragma unroll
            for (int mt = 0; mt < 2; mt++)
                #pragma unroll
                for (int nt = 0; nt < NT; nt++)
                    mma_f16(acc[mt][nt], a[mt], b[nt]);
        }
    }

    // ---- epilogue ----
    int g = lane >> 2, tig = lane & 3;
    #pragma unroll
    for (int mt = 0; mt < 2; mt++) {
        #pragma unroll
        for (int nt = 0; nt < NT; nt++) {
            int col = bx * 128 + wn * WNT + nt * 8 + 2 * tig;
            #pragma unroll
            for (int half = 0; half < 2; half++) {
                int row = by * MTILE + wm * 32 + mt * 16 + g + half * 8;
                float v0 = acc[mt][nt][half * 2 + 0];
                float v1 = acc[mt][nt][half * 2 + 1];
                if (D32) {
                    if (col < N) {
                        float o0 = v0, o1 = v1;
                        if (bias) { o0 += bias[col]; if (col + 1 < N) o1 += bias[col + 1]; }
                        if (Rres) { o0 += Rres[(size_t)row * N + col];
                                    if (col + 1 < N) o1 += Rres[(size_t)row * N + col + 1]; }
                        D32[(size_t)row * N + col] = o0;
                        if (col + 1 < N) D32[(size_t)row * N + col + 1] = o1;
                    }
                } else {
                    size_t rb2 = (size_t)row * 2 * N;
                    #pragma unroll
                    for (int e = 0; e < 2; e++) {
                        int c = col + e;
                        float v = e ? v1 : v0;
                        if (bias) v += bias[c];
                        if (relu) v = fmaxf(v, 0.f);
                        __half hi = __float2half(v);
                        __half lo = __float2half(v - __half2float(hi));
                        D2[rb2 + c]     = hi;
                        D2[rb2 + N + c] = lo;
                    }
                }
            }
        }
    }
}

// ================= fused causal attention (reads fused qkv), fp16 2-term out ======
#define ATTN_SMEM_FLOATS (Tt*HSz + Tt*129)
__global__ void attn_kernel(const float* __restrict__ qkv, __half* __restrict__ out2) {
    extern __shared__ char smem_raw[];
    float* smem = (float*)smem_raw;
    float* kv = smem;
    float* sc = smem + Tt * HSz;
    int b = blockIdx.x >> 2;
    int h = blockIdx.x & 3;
    int tid = threadIdx.x;
    size_t base = (size_t)b * Tt * QS + (size_t)h * HSz;

    for (int i = tid; i < Tt * HSz; i += 128) {
        int r = i >> 6, d = i & 63;
        kv[i] = qkv[base + Cc + (size_t)r * QS + d];       // K
    }
    __syncthreads();

    float qr[HSz];
    #pragma unroll
    for (int d = 0; d < HSz; d += 4) {
        float4 t4 = *(const float4*)&qkv[base + (size_t)tid * QS + d];
        qr[d] = t4.x; qr[d+1] = t4.y; qr[d+2] = t4.z; qr[d+3] = t4.w;
    }

    const float scale = 0.0625f;   // C^-0.5 (matches reference)
    float* myrow = sc + tid * 129;
    float mx = -1e30f;
    for (int j = 0; j <= tid; j++) {
        const float4* kj4 = (const float4*)(kv + j * HSz);
        float s0 = 0.f, s1 = 0.f, s2 = 0.f, s3 = 0.f;
        #pragma unroll
        for (int d4 = 0; d4 < 16; d4++) {
            float4 t = kj4[d4];
            s0 += qr[d4*4+0] * t.x;
            s1 += qr[d4*4+1] * t.y;
            s2 += qr[d4*4+2] * t.z;
            s3 += qr[d4*4+3] * t.w;
        }
        float s = ((s0 + s1) + (s2 + s3)) * scale;
        myrow[j] = s;
        mx = fmaxf(mx, s);
    }
    float sum = 0.f;
    for (int j = 0; j <= tid; j++) {
        float e = __expf(myrow[j] - mx);
        myrow[j] = e;
        sum += e;
    }
    float inv = 1.0f / sum;

    __syncthreads();
    for (int i = tid; i < Tt * HSz; i += 128) {
        int r = i >> 6, d = i & 63;
        kv[i] = qkv[base + 2 * Cc + (size_t)r * QS + d];   // V
    }
    __syncthreads();

    float acc[HSz];
    #pragma unroll
    for (int d = 0; d < HSz; d++) acc[d] = 0.f;
    for (int j = 0; j <= tid; j++) {
        float w = myrow[j] * inv;
        const float4* vj4 = (const float4*)(kv + j * HSz);
        #pragma unroll
        for (int d4 = 0; d4 < 16; d4++) {
            float4 t = vj4[d4];
            acc[d4*4+0] += w * t.x;
            acc[d4*4+1] += w * t.y;
            acc[d4*4+2] += w * t.z;
            acc[d4*4+3] += w * t.w;
        }
    }
    int row = b * Tt + tid;
    size_t o = (size_t)row * K1 + h * HSz;
    #pragma unroll
    for (int d = 0; d < HSz; d++) {
        float vv = acc[d];
        __half hi = __float2half(vv);
        __half lo = __float2half(vv - __half2float(hi));
        out2[o + d]      = hi;
        out2[o + Cc + d] = lo;
    }
}

// ================= host orchestration =================
extern "C" void kernel_launch(void* const* d_in, const int* in_sizes, int n_in,
                              void* d_out, int out_size) {
    const int*   idx    = (const int*)  d_in[0];
    const float* tok    = (const float*)d_in[1];
    const float* pos    = (const float*)d_in[2];
    const float* ln1_g  = (const float*)d_in[3];
    const float* ln1_b  = (const float*)d_in[4];
    const float* wq     = (const float*)d_in[5];
    const float* wk     = (const float*)d_in[6];
    const float* wv     = (const float*)d_in[7];
    const float* proj_w = (const float*)d_in[8];
    const float* proj_b = (const float*)d_in[9];
    const float* ln2_g  = (const float*)d_in[10];
    const float* ln2_b  = (const float*)d_in[11];
    const float* w1     = (const float*)d_in[12];
    const float* b1     = (const float*)d_in[13];
    const float* w2     = (const float*)d_in[14];
    const float* b2     = (const float*)d_in[15];
    const float* lnf_g  = (const float*)d_in[16];
    const float* lnf_b  = (const float*)d_in[17];
    const float* lm_w   = (const float*)d_in[18];
    const float* lm_b   = (const float*)d_in[19];
    float* out = (float*)d_out;

    float *x, *qkv;
    __half *a2, *ff2, *bqkv, *bp, *bw1, *bw2, *blm;
    cudaGetSymbolAddress((void**)&x,    g_x);
    cudaGetSymbolAddress((void**)&qkv,  g_qkv);
    cudaGetSymbolAddress((void**)&a2,   g_act2);
    cudaGetSymbolAddress((void**)&ff2,  g_ff2);
    cudaGetSymbolAddress((void**)&bqkv, g_bqkv);
    cudaGetSymbolAddress((void**)&bp,   g_bp);
    cudaGetSymbolAddress((void**)&bw1,  g_bw1);
    cudaGetSymbolAddress((void**)&bw2,  g_bw2);
    cudaGetSymbolAddress((void**)&blm,  g_blm);

    cudaFuncSetAttribute(gemm_tc<64,4>,  cudaFuncAttributeMaxDynamicSharedMemorySize, GEMM_SMEM);
    cudaFuncSetAttribute(gemm_tc<128,3>, cudaFuncAttributeMaxDynamicSharedMemorySize, GEMM_SMEM);
    const int attn_smem = ATTN_SMEM_FLOATS * (int)sizeof(float);
    cudaFuncSetAttribute(attn_kernel, cudaFuncAttributeMaxDynamicSharedMemorySize, attn_smem);

    // ---- weight transpose to fp16 duplicated [n, 2K] (per replay; deterministic) ----
    dim3 wbk(32, 8);
    const size_t LQKV = (size_t)QS * K1;
    wsplit_f16_kernel<<<dim3(Cc/32, Cc/32, Ll), wbk>>>(wq,     bqkv,                   Cc,   Cc, LQKV);
    wsplit_f16_kernel<<<dim3(Cc/32, Cc/32, Ll), wbk>>>(wk,     bqkv + (size_t)Cc*K1,   Cc,   Cc, LQKV);
    wsplit_f16_kernel<<<dim3(Cc/32, Cc/32, Ll), wbk>>>(wv,     bqkv + (size_t)2*Cc*K1, Cc,   Cc, LQKV);
    wsplit_f16_kernel<<<dim3(Cc/32, Cc/32, Ll), wbk>>>(proj_w, bp,   Cc,   Cc, (size_t)Cc*K1);
    wsplit_f16_kernel<<<dim3(DFFz/32, Cc/32, Ll), wbk>>>(w1,   bw1,  Cc,   DFFz, (size_t)DFFz*K1);
    wsplit_f16_kernel<<<dim3(Cc/32, DFFz/32, Ll), wbk>>>(w2,   bw2,  DFFz, Cc, (size_t)Cc*K2);
    wsplit_f16_kernel<<<dim3(VPAD/32, Cc/32, 1),  wbk>>>(lm_w, blm,  Cc,   Vv, 0);

    embed_kernel<<<MROWS, Cc>>>(idx, tok, pos, x);

    dim3 lnb(256, 2);
    dim3 gQ (QS   / 128, MROWS / 64);    // (6, 256)  = 1536 CTAs
    dim3 gC (Cc   / 128, MROWS / 64);    // (2, 256)  = 512 CTAs
    dim3 gF (DFFz / 128, MROWS / 64);    // (8, 256)  = 2048 CTAs
    dim3 gV (VPAD / 128, MROWS / 128);   // (79, 128) = 10112 CTAs (head keeps 128-tile)

    for (int l = 0; l < Ll; l++) {
        ln_split_kernel<<<MROWS/2, lnb>>>(x, ln1_g + (size_t)l*Cc, ln1_b + (size_t)l*Cc, a2);
        gemm_tc<64,4><<<gQ, 256, GEMM_SMEM>>>(a2, bqkv + (size_t)l*LQKV, nullptr, nullptr,
                                              qkv, nullptr, K1, QS, 0);
        attn_kernel<<<Bb*Hh, 128, attn_smem>>>(qkv, a2);
        gemm_tc<64,4><<<gC, 256, GEMM_SMEM>>>(a2, bp + (size_t)l*Cc*K1, proj_b + (size_t)l*Cc,
                                              x, x, nullptr, K1, Cc, 0);
        ln_split_kernel<<<MROWS/2, lnb>>>(x, ln2_g + (size_t)l*Cc, ln2_b + (size_t)l*Cc, a2);
        gemm_tc<64,4><<<gF, 256, GEMM_SMEM>>>(a2, bw1 + (size_t)l*DFFz*K1, b1 + (size_t)l*DFFz,
                                              nullptr, nullptr, ff2, K1, DFFz, 1);
        gemm_tc<64,4><<<gC, 256, GEMM_SMEM>>>(ff2, bw2 + (size_t)l*Cc*K2, b2 + (size_t)l*Cc,
                                              x, x, nullptr, K2, Cc, 0);
    }

    ln_split_kernel<<<MROWS/2, lnb>>>(x, lnf_g, lnf_b, a2);
    gemm_tc<128,3><<<gV, 256, GEMM_SMEM>>>(a2, blm, lm_b, nullptr, out, nullptr, K1, Vv, 0);
}

// round 12
// speedup vs baseline: 1.4011x; 1.4011x over previous
#include <cuda_runtime.h>
#include <cuda_bf16.h>
#include <cuda_fp16.h>
#include <cstdint>
#include <cstddef>

#define Bb   128
#define Tt   128
#define Cc   256
#define Hh   4
#define HSz  64
#define Ll   6
#define Vv   10000
#define DFFz 1024
#define MROWS (Bb*Tt)   // 16384
#define VPAD 10112      // ceil(10000/128)*128
#define QS   (3*Cc)     // fused qkv row stride (768)
#define KLN  (2*Cc)     // 512: 2-term fp16 acts (LN outputs -> QKV, FF1)

// ================= scratch (device globals) =================
__device__ __align__(256) float g_x  [MROWS * Cc];
__device__ __align__(256) float g_qkv[MROWS * QS];
__device__ __align__(256) __half g_act2[MROWS * KLN];         // LN 2-term [M,512] / single [M,256]
__device__ __align__(256) __half g_ff  [MROWS * DFFz];        // ff acts single fp16 [M, 1024]
__device__ __align__(256) __half g_bqkv[Ll * QS   * KLN];     // dup [768, 512] per layer
__device__ __align__(256) __half g_bp  [Ll * Cc   * Cc];      // single [256, 256]
__device__ __align__(256) __half g_bw1 [Ll * DFFz * KLN];     // dup [1024, 512]
__device__ __align__(256) __half g_bw2 [Ll * Cc   * DFFz];    // single [256, 1024]
__device__ __align__(256) __half g_blm [VPAD * Cc];           // single [10112, 256]

// ================= PTX helpers (arch-agnostic, valid on sm_103) =====
__device__ __forceinline__ uint32_t smem_u32(const void* p) {
    uint32_t a;
    asm("{ .reg .u64 t; cvta.to.shared.u64 t, %1; cvt.u32.u64 %0, t; }" : "=r"(a) : "l"(p));
    return a;
}
__device__ __forceinline__ void cp_async16(uint32_t saddr, const void* gaddr) {
    asm volatile("cp.async.cg.shared.global [%0], [%1], 16;" :: "r"(saddr), "l"(gaddr));
}
__device__ __forceinline__ void cp_commit() { asm volatile("cp.async.commit_group;" ::: "memory"); }
template <int N>
__device__ __forceinline__ void cp_wait() { asm volatile("cp.async.wait_group %0;" :: "n"(N) : "memory"); }

__device__ __forceinline__ void ldm_x4(uint32_t& r0, uint32_t& r1, uint32_t& r2, uint32_t& r3,
                                       uint32_t addr) {
    asm volatile("ldmatrix.sync.aligned.m8n8.x4.shared.b16 {%0,%1,%2,%3}, [%4];"
                 : "=r"(r0), "=r"(r1), "=r"(r2), "=r"(r3) : "r"(addr));
}
__device__ __forceinline__ void mma_f16(float* d, const uint32_t* a, const uint32_t* b) {
    asm volatile("mma.sync.aligned.m16n8k16.row.col.f32.f16.f16.f32 "
                 "{%0,%1,%2,%3}, {%4,%5,%6,%7}, {%8,%9}, {%0,%1,%2,%3};"
                 : "+f"(d[0]), "+f"(d[1]), "+f"(d[2]), "+f"(d[3])
                 : "r"(a[0]), "r"(a[1]), "r"(a[2]), "r"(a[3]), "r"(b[0]), "r"(b[1]));
}

// ================= embedding =================
__global__ void embed_kernel(const int* __restrict__ idx, const float* __restrict__ tok,
                             const float* __restrict__ pos, float* __restrict__ x) {
    int bt = blockIdx.x;
    int t  = bt % Tt;
    int tokid = idx[bt];
    int c = threadIdx.x;
    x[(size_t)bt * Cc + c] = tok[(size_t)tokid * Cc + c] + pos[(size_t)t * Cc + c];
}

// ================= LN core =================
__device__ __forceinline__ float ln_value(const float* __restrict__ x,
                                          const float* __restrict__ gam,
                                          const float* __restrict__ bet,
                                          int row, int tid, int ly) {
    float v = x[(size_t)row * Cc + tid];
    float s = v, sq = v * v;
    #pragma unroll
    for (int o = 16; o > 0; o >>= 1) {
        s  += __shfl_xor_sync(0xFFFFFFFFu, s,  o);
        sq += __shfl_xor_sync(0xFFFFFFFFu, sq, o);
    }
    __shared__ float ws[2][8], wsq[2][8];
    if ((tid & 31) == 0) { ws[ly][tid >> 5] = s; wsq[ly][tid >> 5] = sq; }
    __syncthreads();
    float S = 0.f, Q = 0.f;
    #pragma unroll
    for (int i = 0; i < 8; i++) { S += ws[ly][i]; Q += wsq[ly][i]; }
    float mean = S * (1.0f / Cc);
    float var  = Q * (1.0f / Cc) - mean * mean;
    float inv  = rsqrtf(var + 1e-5f);
    return (v - mean) * inv * gam[tid] + bet[tid];
}

// LN -> 2-term fp16 [M, 512] (exact acts), 2 rows/block
__global__ void ln_split2_kernel(const float* __restrict__ x, const float* __restrict__ gam,
                                 const float* __restrict__ bet, __half* __restrict__ out2) {
    int row = blockIdx.x * 2 + threadIdx.y;
    int tid = threadIdx.x;
    float y = ln_value(x, gam, bet, row, tid, threadIdx.y);
    __half hi = __float2half(y);
    __half lo = __float2half(y - __half2float(hi));
    size_t o = (size_t)row * KLN;
    out2[o + tid]      = hi;
    out2[o + Cc + tid] = lo;
}

// LN -> single fp16 [M, 256], 2 rows/block (head input)
__global__ void ln_single_kernel(const float* __restrict__ x, const float* __restrict__ gam,
                                 const float* __restrict__ bet, __half* __restrict__ out1) {
    int row = blockIdx.x * 2 + threadIdx.y;
    int tid = threadIdx.x;
    float y = ln_value(x, gam, bet, row, tid, threadIdx.y);
    out1[(size_t)row * Cc + tid] = __float2half(y);
}

// ================= weight transpose fp16: W[K,N] -> out[n, (1+dup)K] ======
__global__ void wsplit_f16_kernel(const float* __restrict__ W, __half* __restrict__ out,
                                  int K, int N, size_t lstride, int dup) {
    int l = blockIdx.z;
    W   += (size_t)l * K * N;
    out += (size_t)l * lstride;
    __shared__ float tile[32][33];
    int k0 = blockIdx.y * 32, n0 = blockIdx.x * 32;
    int tx = threadIdx.x, ty = threadIdx.y;   // 32 x 8
    #pragma unroll
    for (int i = 0; i < 32; i += 8) {
        int k = k0 + ty + i, n = n0 + tx;
        tile[ty + i][tx] = (n < N) ? W[(size_t)k * N + n] : 0.f;
    }
    __syncthreads();
    int rstride = (dup ? 2 : 1) * K;
    #pragma unroll
    for (int i = 0; i < 32; i += 8) {
        int n = n0 + ty + i, k = k0 + tx;
        __half h = __float2half(tile[tx][ty + i]);
        size_t rb = (size_t)n * rstride;
        out[rb + k] = h;
        if (dup) out[rb + K + k] = h;
    }
}

// ================= HMMA fp16 GEMM, 128x128 tile, 3-stage cp.async, 2 CTAs/SM ====
// D[M, N] = A[M, Kfull] @ B[N, Kfull]^T, fp32 accum.
// Outputs: D32 (f32, +bias/+residual) or D2 (single fp16, +bias/+relu).
#define LDA 72
#define CHELE (128 * LDA)
#define STAGE (2 * CHELE)
#define GEMM_SMEM (3 * STAGE * 2)          // 110592 bytes

__global__ void __launch_bounds__(256, 2)
gemm_tc(const __half* __restrict__ A2, const __half* __restrict__ B2,
        const float* __restrict__ bias, const float* __restrict__ Rres,
        float* __restrict__ D32, __half* __restrict__ D2,
        int Kfull, int N, int relu) {
    extern __shared__ char smem_raw[];
    uint32_t sb = smem_u32(smem_raw);
    int tid = threadIdx.x, lane = tid & 31, wid = tid >> 5;
    int wm = wid & 3, wn = wid >> 2;       // 4Mx2N warps, warp tile 32x64
    int bx = blockIdx.x, by = blockIdx.y;

    const __half* Abase = A2 + (size_t)(by * 128) * Kfull;
    const __half* Bbase = B2 + (size_t)(bx * 128) * Kfull;
    int nch = Kfull >> 6;

    float acc[2][8][4];
    #pragma unroll
    for (int mt = 0; mt < 2; mt++)
        #pragma unroll
        for (int nt = 0; nt < 8; nt++)
            #pragma unroll
            for (int i = 0; i < 4; i++) acc[mt][nt][i] = 0.f;

    int lrow[4], lunit[4];
    #pragma unroll
    for (int j = 0; j < 4; j++) {
        int lin = tid + j * 256;
        lrow[j]  = lin >> 3;
        lunit[j] = (lin & 7) << 3;
    }

    auto issue_load = [&](int kc, int buf) {
        const __half* Ag = Abase + kc * 64;
        const __half* Bg = Bbase + kc * 64;
        uint32_t sA = sb + (uint32_t)(buf * STAGE) * 2;
        uint32_t sB = sA + (uint32_t)CHELE * 2;
        #pragma unroll
        for (int j = 0; j < 4; j++) {
            cp_async16(sA + (uint32_t)(lrow[j] * LDA + lunit[j]) * 2,
                       Ag + (size_t)lrow[j] * Kfull + lunit[j]);
            cp_async16(sB + (uint32_t)(lrow[j] * LDA + lunit[j]) * 2,
                       Bg + (size_t)lrow[j] * Kfull + lunit[j]);
        }
        cp_commit();
    };

    issue_load(0, 0);
    if (nch > 1) issue_load(1, 1);

    int a_row = wm * 32 + (lane & 15);
    int a_kc  = (lane >> 4) * 8;
    int b_row = wn * 64 + (lane & 7) + ((lane >> 4) << 3);
    int b_kc  = (lane & 8);

    for (int kc = 0; kc < nch; kc++) {
        if (kc + 1 < nch) cp_wait<1>(); else cp_wait<0>();
        __syncthreads();           // orders prior-buffer reads before reissue below
        if (kc + 2 < nch) issue_load(kc + 2, (kc + 2) % 3);

        int buf = kc % 3;
        uint32_t sA = sb + (uint32_t)(buf * STAGE) * 2;
        uint32_t sB = sA + (uint32_t)CHELE * 2;

        #pragma unroll
        for (int ks = 0; ks < 4; ks++) {
            uint32_t a[2][4], b[8][2];
            #pragma unroll
            for (int mt = 0; mt < 2; mt++) {
                uint32_t addr = sA + (uint32_t)((a_row + mt * 16) * LDA + ks * 16 + a_kc) * 2;
                ldm_x4(a[mt][0], a[mt][1], a[mt][2], a[mt][3], addr);
            }
            #pragma unroll
            for (int ntp = 0; ntp < 4; ntp++) {
                uint32_t addr = sB + (uint32_t)((b_row + ntp * 16) * LDA + ks * 16 + b_kc) * 2;
                ldm_x4(b[ntp*2][0], b[ntp*2][1], b[ntp*2+1][0], b[ntp*2+1][1], addr);
            }
            #pragma unroll
            for (int mt = 0; mt < 2; mt++)
                #pragma unroll
                for (int nt = 0; nt < 8; nt++)
                    mma_f16(acc[mt][nt], a[mt], b[nt]);
        }
    }

    // ---- epilogue ----
    int g = lane >> 2, tig = lane & 3;
    #pragma unroll
    for (int mt = 0; mt < 2; mt++) {
        #pragma unroll
        for (int nt = 0; nt < 8; nt++) {
            int col = bx * 128 + wn * 64 + nt * 8 + 2 * tig;
            #pragma unroll
            for (int half = 0; half < 2; half++) {
                int row = by * 128 + wm * 32 + mt * 16 + g + half * 8;
                float v0 = acc[mt][nt][half * 2 + 0];
                float v1 = acc[mt][nt][half * 2 + 1];
                if (D32) {
                    if (col < N) {
                        float o0 = v0, o1 = v1;
                        if (bias) { o0 += bias[col]; if (col + 1 < N) o1 += bias[col + 1]; }
                        if (Rres) { o0 += Rres[(size_t)row * N + col];
                                    if (col + 1 < N) o1 += Rres[(size_t)row * N + col + 1]; }
                        D32[(size_t)row * N + col] = o0;
                        if (col + 1 < N) D32[(size_t)row * N + col + 1] = o1;
                    }
                } else {
                    #pragma unroll
                    for (int e = 0; e < 2; e++) {
                        int c = col + e;
                        if (c < N) {
                            float v = e ? v1 : v0;
                            if (bias) v += bias[c];
                            if (relu) v = fmaxf(v, 0.f);
                            D2[(size_t)row * N + c] = __float2half(v);
                        }
                    }
                }
            }
        }
    }
}

// ================= fused causal attention (reads fused qkv), single fp16 out =====
#define ATTN_SMEM_FLOATS (Tt*HSz + Tt*129)
__global__ void attn_kernel(const float* __restrict__ qkv, __half* __restrict__ out1) {
    extern __shared__ char smem_raw[];
    float* smem = (float*)smem_raw;
    float* kv = smem;
    float* sc = smem + Tt * HSz;
    int b = blockIdx.x >> 2;
    int h = blockIdx.x & 3;
    int tid = threadIdx.x;
    size_t base = (size_t)b * Tt * QS + (size_t)h * HSz;

    for (int i = tid; i < Tt * HSz; i += 128) {
        int r = i >> 6, d = i & 63;
        kv[i] = qkv[base + Cc + (size_t)r * QS + d];       // K
    }
    __syncthreads();

    float qr[HSz];
    #pragma unroll
    for (int d = 0; d < HSz; d += 4) {
        float4 t4 = *(const float4*)&qkv[base + (size_t)tid * QS + d];
        qr[d] = t4.x; qr[d+1] = t4.y; qr[d+2] = t4.z; qr[d+3] = t4.w;
    }

    const float scale = 0.0625f;   // C^-0.5 (matches reference)
    float* myrow = sc + tid * 129;
    float mx = -1e30f;
    for (int j = 0; j <= tid; j++) {
        const float4* kj4 = (const float4*)(kv + j * HSz);
        float s0 = 0.f, s1 = 0.f, s2 = 0.f, s3 = 0.f;
        #pragma unroll
        for (int d4 = 0; d4 < 16; d4++) {
            float4 t = kj4[d4];
            s0 += qr[d4*4+0] * t.x;
            s1 += qr[d4*4+1] * t.y;
            s2 += qr[d4*4+2] * t.z;
            s3 += qr[d4*4+3] * t.w;
        }
        float s = ((s0 + s1) + (s2 + s3)) * scale;
        myrow[j] = s;
        mx = fmaxf(mx, s);
    }
    float sum = 0.f;
    for (int j = 0; j <= tid; j++) {
        float e = __expf(myrow[j] - mx);
        myrow[j] = e;
        sum += e;
    }
    float inv = 1.0f / sum;

    __syncthreads();
    for (int i = tid; i < Tt * HSz; i += 128) {
        int r = i >> 6, d = i & 63;
        kv[i] = qkv[base + 2 * Cc + (size_t)r * QS + d];   // V
    }
    __syncthreads();

    float acc[HSz];
    #pragma unroll
    for (int d = 0; d < HSz; d++) acc[d] = 0.f;
    for (int j = 0; j <= tid; j++) {
        float w = myrow[j] * inv;
        const float4* vj4 = (const float4*)(kv + j * HSz);
        #pragma unroll
        for (int d4 = 0; d4 < 16; d4++) {
            float4 t = vj4[d4];
            acc[d4*4+0] += w * t.x;
            acc[d4*4+1] += w * t.y;
            acc[d4*4+2] += w * t.z;
            acc[d4*4+3] += w * t.w;
        }
    }
    int row = b * Tt + tid;
    size_t o = (size_t)row * Cc + h * HSz;
    #pragma unroll
    for (int d = 0; d < HSz; d++)
        out1[o + d] = __float2half(acc[d]);
}

// ================= host orchestration =================
extern "C" void kernel_launch(void* const* d_in, const int* in_sizes, int n_in,
                              void* d_out, int out_size) {
    const int*   idx    = (const int*)  d_in[0];
    const float* tok    = (const float*)d_in[1];
    const float* pos    = (const float*)d_in[2];
    const float* ln1_g  = (const float*)d_in[3];
    const float* ln1_b  = (const float*)d_in[4];
    const float* wq     = (const float*)d_in[5];
    const float* wk     = (const float*)d_in[6];
    const float* wv     = (const float*)d_in[7];
    const float* proj_w = (const float*)d_in[8];
    const float* proj_b = (const float*)d_in[9];
    const float* ln2_g  = (const float*)d_in[10];
    const float* ln2_b  = (const float*)d_in[11];
    const float* w1     = (const float*)d_in[12];
    const float* b1     = (const float*)d_in[13];
    const float* w2     = (const float*)d_in[14];
    const float* b2     = (const float*)d_in[15];
    const float* lnf_g  = (const float*)d_in[16];
    const float* lnf_b  = (const float*)d_in[17];
    const float* lm_w   = (const float*)d_in[18];
    const float* lm_b   = (const float*)d_in[19];
    float* out = (float*)d_out;

    float *x, *qkv;
    __half *a2, *ff, *bqkv, *bp, *bw1, *bw2, *blm;
    cudaGetSymbolAddress((void**)&x,    g_x);
    cudaGetSymbolAddress((void**)&qkv,  g_qkv);
    cudaGetSymbolAddress((void**)&a2,   g_act2);
    cudaGetSymbolAddress((void**)&ff,   g_ff);
    cudaGetSymbolAddress((void**)&bqkv, g_bqkv);
    cudaGetSymbolAddress((void**)&bp,   g_bp);
    cudaGetSymbolAddress((void**)&bw1,  g_bw1);
    cudaGetSymbolAddress((void**)&bw2,  g_bw2);
    cudaGetSymbolAddress((void**)&blm,  g_blm);

    cudaFuncSetAttribute(gemm_tc, cudaFuncAttributeMaxDynamicSharedMemorySize, GEMM_SMEM);
    const int attn_smem = ATTN_SMEM_FLOATS * (int)sizeof(float);
    cudaFuncSetAttribute(attn_kernel, cudaFuncAttributeMaxDynamicSharedMemorySize, attn_smem);

    dim3 wbk(32, 8);
    dim3 lnb(256, 2);
    const size_t LQKV = (size_t)QS * KLN;   // per-layer stride of fused qkv weight
    dim3 gQ (QS   / 128, MROWS / 128);      // (6, 128)
    dim3 gC (Cc   / 128, MROWS / 128);      // (2, 128)
    dim3 gF (DFFz / 128, MROWS / 128);      // (8, 128)
    dim3 gV (VPAD / 128, MROWS / 128);      // (79, 128)

    // ---- launches 0-2: qkv weight splits (dup) ----
    wsplit_f16_kernel<<<dim3(Cc/32, Cc/32, Ll), wbk>>>(wq, bqkv,                    Cc, Cc, LQKV, 1);
    wsplit_f16_kernel<<<dim3(Cc/32, Cc/32, Ll), wbk>>>(wk, bqkv + (size_t)Cc*KLN,   Cc, Cc, LQKV, 1);
    wsplit_f16_kernel<<<dim3(Cc/32, Cc/32, Ll), wbk>>>(wv, bqkv + (size_t)2*Cc*KLN, Cc, Cc, LQKV, 1);
    // ---- launch 3: embed; 4: ln1(l=0); 5: QKV gemm(l=0)  [ncu -s 5 profiles this] ----
    embed_kernel<<<MROWS, Cc>>>(idx, tok, pos, x);
    ln_split2_kernel<<<MROWS/2, lnb>>>(x, ln1_g, ln1_b, a2);
    gemm_tc<<<gQ, 256, GEMM_SMEM>>>(a2, bqkv, nullptr, nullptr, qkv, nullptr, KLN, QS, 0);
    // ---- remaining weight preps ----
    wsplit_f16_kernel<<<dim3(Cc/32, Cc/32, Ll), wbk>>>(proj_w, bp, Cc, Cc, (size_t)Cc*Cc, 0);
    wsplit_f16_kernel<<<dim3(DFFz/32, Cc/32, Ll), wbk>>>(w1, bw1, Cc, DFFz, (size_t)DFFz*KLN, 1);
    wsplit_f16_kernel<<<dim3(Cc/32, DFFz/32, Ll), wbk>>>(w2, bw2, DFFz, Cc, (size_t)Cc*DFFz, 0);
    wsplit_f16_kernel<<<dim3(VPAD/32, Cc/32, 1),  wbk>>>(lm_w, blm, Cc, Vv, 0, 0);

    for (int l = 0; l < Ll; l++) {
        if (l > 0) {
            ln_split2_kernel<<<MROWS/2, lnb>>>(x, ln1_g + (size_t)l*Cc, ln1_b + (size_t)l*Cc, a2);
            gemm_tc<<<gQ, 256, GEMM_SMEM>>>(a2, bqkv + (size_t)l*LQKV, nullptr, nullptr,
                                            qkv, nullptr, KLN, QS, 0);
        }
        attn_kernel<<<Bb*Hh, 128, attn_smem>>>(qkv, a2);   // single fp16 [M,256]
        gemm_tc<<<gC, 256, GEMM_SMEM>>>(a2, bp + (size_t)l*Cc*Cc, proj_b + (size_t)l*Cc,
                                        x, x, nullptr, Cc, Cc, 0);
        ln_split2_kernel<<<MROWS/2, lnb>>>(x, ln2_g + (size_t)l*Cc, ln2_b + (size_t)l*Cc, a2);
        gemm_tc<<<gF, 256, GEMM_SMEM>>>(a2, bw1 + (size_t)l*DFFz*KLN, b1 + (size_t)l*DFFz,
                                        nullptr, nullptr, ff, KLN, DFFz, 1);   // relu fp16 out
        gemm_tc<<<gC, 256, GEMM_SMEM>>>(ff, bw2 + (size_t)l*Cc*DFFz, b2 + (size_t)l*Cc,
                                        x, x, nullptr, DFFz, Cc, 0);
    }

    ln_single_kernel<<<MROWS/2, lnb>>>(x, lnf_g, lnf_b, a2);
    gemm_tc<<<gV, 256, GEMM_SMEM>>>(a2, blm, lm_b, nullptr, out, nullptr, Cc, Vv, 0);
}

// round 14
// speedup vs baseline: 1.6341x; 1.1663x over previous
#include <cuda_runtime.h>
#include <cuda_bf16.h>
#include <cuda_fp16.h>
#include <cstdint>
#include <cstddef>

#define Bb   128
#define Tt   128
#define Cc   256
#define Hh   4
#define HSz  64
#define Ll   6
#define Vv   10000
#define DFFz 1024
#define MROWS (Bb*Tt)   // 16384
#define VPAD 10112      // ceil(10000/128)*128
#define QS   (3*Cc)     // fused qkv row stride (768)
#define KLN  (2*Cc)     // 512: 2-term fp16 acts (LN outputs -> QKV, FF1)

// ================= scratch (device globals) =================
__device__ __align__(256) float g_x  [MROWS * Cc];
__device__ __align__(256) float g_qkv[MROWS * QS];
__device__ __align__(256) __half g_act2[MROWS * KLN];         // LN 2-term [M,512] / single [M,256]
__device__ __align__(256) __half g_ff  [MROWS * DFFz];        // ff acts single fp16 [M, 1024]
__device__ __align__(256) __half g_bqkv[Ll * QS   * KLN];     // dup [768, 512] per layer
__device__ __align__(256) __half g_bp  [Ll * Cc   * Cc];      // single [256, 256]
__device__ __align__(256) __half g_bw1 [Ll * DFFz * KLN];     // dup [1024, 512]
__device__ __align__(256) __half g_bw2 [Ll * Cc   * DFFz];    // single [256, 1024]
__device__ __align__(256) __half g_blm [VPAD * Cc];           // single [10112, 256]

// ================= PTX helpers (arch-agnostic, valid on sm_103) =====
__device__ __forceinline__ uint32_t smem_u32(const void* p) {
    uint32_t a;
    asm("{ .reg .u64 t; cvta.to.shared.u64 t, %1; cvt.u32.u64 %0, t; }" : "=r"(a) : "l"(p));
    return a;
}
__device__ __forceinline__ void cp_async16(uint32_t saddr, const void* gaddr) {
    asm volatile("cp.async.cg.shared.global [%0], [%1], 16;" :: "r"(saddr), "l"(gaddr));
}
__device__ __forceinline__ void cp_commit() { asm volatile("cp.async.commit_group;" ::: "memory"); }
template <int N>
__device__ __forceinline__ void cp_wait() { asm volatile("cp.async.wait_group %0;" :: "n"(N) : "memory"); }

__device__ __forceinline__ void ldm_x4(uint32_t& r0, uint32_t& r1, uint32_t& r2, uint32_t& r3,
                                       uint32_t addr) {
    asm volatile("ldmatrix.sync.aligned.m8n8.x4.shared.b16 {%0,%1,%2,%3}, [%4];"
                 : "=r"(r0), "=r"(r1), "=r"(r2), "=r"(r3) : "r"(addr));
}
__device__ __forceinline__ void mma_f16(float* d, const uint32_t* a, const uint32_t* b) {
    asm volatile("mma.sync.aligned.m16n8k16.row.col.f32.f16.f16.f32 "
                 "{%0,%1,%2,%3}, {%4,%5,%6,%7}, {%8,%9}, {%0,%1,%2,%3};"
                 : "+f"(d[0]), "+f"(d[1]), "+f"(d[2]), "+f"(d[3])
                 : "r"(a[0]), "r"(a[1]), "r"(a[2]), "r"(a[3]), "r"(b[0]), "r"(b[1]));
}

// ================= embedding =================
__global__ void embed_kernel(const int* __restrict__ idx, const float* __restrict__ tok,
                             const float* __restrict__ pos, float* __restrict__ x) {
    int bt = blockIdx.x;
    int t  = bt % Tt;
    int tokid = idx[bt];
    int c = threadIdx.x;
    x[(size_t)bt * Cc + c] = tok[(size_t)tokid * Cc + c] + pos[(size_t)t * Cc + c];
}

// ================= LN core =================
__device__ __forceinline__ float ln_value(const float* __restrict__ x,
                                          const float* __restrict__ gam,
                                          const float* __restrict__ bet,
                                          int row, int tid, int ly) {
    float v = x[(size_t)row * Cc + tid];
    float s = v, sq = v * v;
    #pragma unroll
    for (int o = 16; o > 0; o >>= 1) {
        s  += __shfl_xor_sync(0xFFFFFFFFu, s,  o);
        sq += __shfl_xor_sync(0xFFFFFFFFu, sq, o);
    }
    __shared__ float ws[2][8], wsq[2][8];
    if ((tid & 31) == 0) { ws[ly][tid >> 5] = s; wsq[ly][tid >> 5] = sq; }
    __syncthreads();
    float S = 0.f, Q = 0.f;
    #pragma unroll
    for (int i = 0; i < 8; i++) { S += ws[ly][i]; Q += wsq[ly][i]; }
    float mean = S * (1.0f / Cc);
    float var  = Q * (1.0f / Cc) - mean * mean;
    float inv  = rsqrtf(var + 1e-5f);
    return (v - mean) * inv * gam[tid] + bet[tid];
}

// LN -> 2-term fp16 [M, 512] (exact acts), 2 rows/block
__global__ void ln_split2_kernel(const float* __restrict__ x, const float* __restrict__ gam,
                                 const float* __restrict__ bet, __half* __restrict__ out2) {
    int row = blockIdx.x * 2 + threadIdx.y;
    int tid = threadIdx.x;
    float y = ln_value(x, gam, bet, row, tid, threadIdx.y);
    __half hi = __float2half(y);
    __half lo = __float2half(y - __half2float(hi));
    size_t o = (size_t)row * KLN;
    out2[o + tid]      = hi;
    out2[o + Cc + tid] = lo;
}

// LN -> single fp16 [M, 256], 2 rows/block (head input)
__global__ void ln_single_kernel(const float* __restrict__ x, const float* __restrict__ gam,
                                 const float* __restrict__ bet, __half* __restrict__ out1) {
    int row = blockIdx.x * 2 + threadIdx.y;
    int tid = threadIdx.x;
    float y = ln_value(x, gam, bet, row, tid, threadIdx.y);
    out1[(size_t)row * Cc + tid] = __float2half(y);
}

// ================= weight transpose fp16: W[K,N] -> out[n, (1+dup)K] ======
__global__ void wsplit_f16_kernel(const float* __restrict__ W, __half* __restrict__ out,
                                  int K, int N, size_t lstride, int dup) {
    int l = blockIdx.z;
    W   += (size_t)l * K * N;
    out += (size_t)l * lstride;
    __shared__ float tile[32][33];
    int k0 = blockIdx.y * 32, n0 = blockIdx.x * 32;
    int tx = threadIdx.x, ty = threadIdx.y;   // 32 x 8
    #pragma unroll
    for (int i = 0; i < 32; i += 8) {
        int k = k0 + ty + i, n = n0 + tx;
        tile[ty + i][tx] = (n < N) ? W[(size_t)k * N + n] : 0.f;
    }
    __syncthreads();
    int rstride = (dup ? 2 : 1) * K;
    #pragma unroll
    for (int i = 0; i < 32; i += 8) {
        int n = n0 + ty + i, k = k0 + tx;
        __half h = __float2half(tile[tx][ty + i]);
        size_t rb = (size_t)n * rstride;
        out[rb + k] = h;
        if (dup) out[rb + K + k] = h;
    }
}

// fused qkv weight split: one launch, z = 3*Ll; which = z%3 picks wq/wk/wv
__global__ void wsplit_qkv_kernel(const float* __restrict__ Wq, const float* __restrict__ Wk,
                                  const float* __restrict__ Wv, __half* __restrict__ out) {
    int which = blockIdx.z % 3;
    int l     = blockIdx.z / 3;
    const float* W = (which == 0) ? Wq : (which == 1) ? Wk : Wv;
    W   += (size_t)l * Cc * Cc;
    out += (size_t)l * QS * KLN + (size_t)which * Cc * KLN;
    __shared__ float tile[32][33];
    int k0 = blockIdx.y * 32, n0 = blockIdx.x * 32;
    int tx = threadIdx.x, ty = threadIdx.y;
    #pragma unroll
    for (int i = 0; i < 32; i += 8) {
        int k = k0 + ty + i, n = n0 + tx;
        tile[ty + i][tx] = W[(size_t)k * Cc + n];
    }
    __syncthreads();
    #pragma unroll
    for (int i = 0; i < 32; i += 8) {
        int n = n0 + ty + i, k = k0 + tx;
        __half h = __float2half(tile[tx][ty + i]);
        size_t rb = (size_t)n * KLN;
        out[rb + k]      = h;
        out[rb + Cc + k] = h;
    }
}

// ================= HMMA fp16 GEMM, 128x128 tile, 3-stage cp.async, 2 CTAs/SM ====
// D[M, N] = A[M, Kfull] @ B[N, Kfull]^T, fp32 accum.
// Epilogue: smem-staged, fully coalesced float4 pass (bias/residual/relu there).
#define LDA 72
#define CHELE (128 * LDA)
#define STAGE (2 * CHELE)
#define GEMM_SMEM (3 * STAGE * 2)          // 110592 bytes
#define LDE 132                            // f32 epilogue stride: 132*4=528B rows, 16B-aligned

__global__ void __launch_bounds__(256, 2)
gemm_tc(const __half* __restrict__ A2, const __half* __restrict__ B2,
        const float* __restrict__ bias, const float* __restrict__ Rres,
        float* __restrict__ D32, __half* __restrict__ D2,
        int Kfull, int N, int relu) {
    extern __shared__ char smem_raw[];
    uint32_t sb = smem_u32(smem_raw);
    int tid = threadIdx.x, lane = tid & 31, wid = tid >> 5;
    int wm = wid & 3, wn = wid >> 2;       // 4Mx2N warps, warp tile 32x64
    int bx = blockIdx.x, by = blockIdx.y;

    const __half* Abase = A2 + (size_t)(by * 128) * Kfull;
    const __half* Bbase = B2 + (size_t)(bx * 128) * Kfull;
    int nch = Kfull >> 6;

    float acc[2][8][4];
    #pragma unroll
    for (int mt = 0; mt < 2; mt++)
        #pragma unroll
        for (int nt = 0; nt < 8; nt++)
            #pragma unroll
            for (int i = 0; i < 4; i++) acc[mt][nt][i] = 0.f;

    int lrow[4], lunit[4];
    #pragma unroll
    for (int j = 0; j < 4; j++) {
        int lin = tid + j * 256;
        lrow[j]  = lin >> 3;
        lunit[j] = (lin & 7) << 3;
    }

    auto issue_load = [&](int kc, int buf) {
        const __half* Ag = Abase + kc * 64;
        const __half* Bg = Bbase + kc * 64;
        uint32_t sA = sb + (uint32_t)(buf * STAGE) * 2;
        uint32_t sB = sA + (uint32_t)CHELE * 2;
        #pragma unroll
        for (int j = 0; j < 4; j++) {
            cp_async16(sA + (uint32_t)(lrow[j] * LDA + lunit[j]) * 2,
                       Ag + (size_t)lrow[j] * Kfull + lunit[j]);
            cp_async16(sB + (uint32_t)(lrow[j] * LDA + lunit[j]) * 2,
                       Bg + (size_t)lrow[j] * Kfull + lunit[j]);
        }
        cp_commit();
    };

    issue_load(0, 0);
    if (nch > 1) issue_load(1, 1);

    int a_row = wm * 32 + (lane & 15);
    int a_kc  = (lane >> 4) * 8;
    int b_row = wn * 64 + (lane & 7) + ((lane >> 4) << 3);
    int b_kc  = (lane & 8);

    for (int kc = 0; kc < nch; kc++) {
        if (kc + 1 < nch) cp_wait<1>(); else cp_wait<0>();
        __syncthreads();
        if (kc + 2 < nch) issue_load(kc + 2, (kc + 2) % 3);

        int buf = kc % 3;
        uint32_t sA = sb + (uint32_t)(buf * STAGE) * 2;
        uint32_t sB = sA + (uint32_t)CHELE * 2;

        #pragma unroll
        for (int ks = 0; ks < 4; ks++) {
            uint32_t a[2][4], b[8][2];
            #pragma unroll
            for (int mt = 0; mt < 2; mt++) {
                uint32_t addr = sA + (uint32_t)((a_row + mt * 16) * LDA + ks * 16 + a_kc) * 2;
                ldm_x4(a[mt][0], a[mt][1], a[mt][2], a[mt][3], addr);
            }
            #pragma unroll
            for (int ntp = 0; ntp < 4; ntp++) {
                uint32_t addr = sB + (uint32_t)((b_row + ntp * 16) * LDA + ks * 16 + b_kc) * 2;
                ldm_x4(b[ntp*2][0], b[ntp*2][1], b[ntp*2+1][0], b[ntp*2+1][1], addr);
            }
            #pragma unroll
            for (int mt = 0; mt < 2; mt++)
                #pragma unroll
                for (int nt = 0; nt < 8; nt++)
                    mma_f16(acc[mt][nt], a[mt], b[nt]);
        }
    }

    // ---- epilogue: scatter acc -> smem, then fully-coalesced pass ----
    __syncthreads();                       // all mainloop smem reads done
    float* st = (float*)smem_raw;          // 128 x LDE f32 tile (67584 B)
    int g = lane >> 2, tig = lane & 3;
    #pragma unroll
    for (int mt = 0; mt < 2; mt++) {
        #pragma unroll
        for (int nt = 0; nt < 8; nt++) {
            int c = wn * 64 + nt * 8 + 2 * tig;
            #pragma unroll
            for (int half = 0; half < 2; half++) {
                int r = wm * 32 + mt * 16 + g + half * 8;
                st[r * LDE + c]     = acc[mt][nt][half * 2 + 0];
                st[r * LDE + c + 1] = acc[mt][nt][half * 2 + 1];
            }
        }
    }
    __syncthreads();
    #pragma unroll
    for (int i = 0; i < 16; i++) {
        int pos = i * 1024 + tid * 4;      // linear over 128x128 tile
        int r = pos >> 7, c = pos & 127;
        int col = bx * 128 + c;
        if (col >= N) continue;            // N%4==0 always -> whole float4 in/out
        int row = by * 128 + r;
        float4 v = *(float4*)&st[r * LDE + c];
        if (bias) {
            float4 bv = *(const float4*)&bias[col];
            v.x += bv.x; v.y += bv.y; v.z += bv.z; v.w += bv.w;
        }
        if (D32) {
            if (Rres) {
                float4 rv = *(const float4*)&Rres[(size_t)row * N + col];
                v.x += rv.x; v.y += rv.y; v.z += rv.z; v.w += rv.w;
            }
            *(float4*)&D32[(size_t)row * N + col] = v;
        } else {
            if (relu) {
                v.x = fmaxf(v.x, 0.f); v.y = fmaxf(v.y, 0.f);
                v.z = fmaxf(v.z, 0.f); v.w = fmaxf(v.w, 0.f);
            }
            __half2* dp = (__half2*)&D2[(size_t)row * N + col];
            dp[0] = __floats2half2_rn(v.x, v.y);
            dp[1] = __floats2half2_rn(v.z, v.w);
        }
    }
}

// ================= fused causal attention (reads fused qkv), single fp16 out =====
#define ATTN_SMEM_FLOATS (Tt*HSz + Tt*129)
__global__ void attn_kernel(const float* __restrict__ qkv, __half* __restrict__ out1) {
    extern __shared__ char smem_raw[];
    float* smem = (float*)smem_raw;
    float* kv = smem;
    float* sc = smem + Tt * HSz;
    int b = blockIdx.x >> 2;
    int h = blockIdx.x & 3;
    int tid = threadIdx.x;
    size_t base = (size_t)b * Tt * QS + (size_t)h * HSz;

    for (int i = tid; i < Tt * HSz; i += 128) {
        int r = i >> 6, d = i & 63;
        kv[i] = qkv[base + Cc + (size_t)r * QS + d];       // K
    }
    __syncthreads();

    float qr[HSz];
    #pragma unroll
    for (int d = 0; d < HSz; d += 4) {
        float4 t4 = *(const float4*)&qkv[base + (size_t)tid * QS + d];
        qr[d] = t4.x; qr[d+1] = t4.y; qr[d+2] = t4.z; qr[d+3] = t4.w;
    }

    const float scale = 0.0625f;   // C^-0.5 (matches reference)
    float* myrow = sc + tid * 129;
    float mx = -1e30f;
    for (int j = 0; j <= tid; j++) {
        const float4* kj4 = (const float4*)(kv + j * HSz);
        float s0 = 0.f, s1 = 0.f, s2 = 0.f, s3 = 0.f;
        #pragma unroll
        for (int d4 = 0; d4 < 16; d4++) {
            float4 t = kj4[d4];
            s0 += qr[d4*4+0] * t.x;
            s1 += qr[d4*4+1] * t.y;
            s2 += qr[d4*4+2] * t.z;
            s3 += qr[d4*4+3] * t.w;
        }
        float s = ((s0 + s1) + (s2 + s3)) * scale;
        myrow[j] = s;
        mx = fmaxf(mx, s);
    }
    float sum = 0.f;
    for (int j = 0; j <= tid; j++) {
        float e = __expf(myrow[j] - mx);
        myrow[j] = e;
        sum += e;
    }
    float inv = 1.0f / sum;

    __syncthreads();
    for (int i = tid; i < Tt * HSz; i += 128) {
        int r = i >> 6, d = i & 63;
        kv[i] = qkv[base + 2 * Cc + (size_t)r * QS + d];   // V
    }
    __syncthreads();

    float acc[HSz];
    #pragma unroll
    for (int d = 0; d < HSz; d++) acc[d] = 0.f;
    for (int j = 0; j <= tid; j++) {
        float w = myrow[j] * inv;
        const float4* vj4 = (const float4*)(kv + j * HSz);
        #pragma unroll
        for (int d4 = 0; d4 < 16; d4++) {
            float4 t = vj4[d4];
            acc[d4*4+0] += w * t.x;
            acc[d4*4+1] += w * t.y;
            acc[d4*4+2] += w * t.z;
            acc[d4*4+3] += w * t.w;
        }
    }
    int row = b * Tt + tid;
    size_t o = (size_t)row * Cc + h * HSz;
    #pragma unroll
    for (int d = 0; d < HSz; d++)
        out1[o + d] = __float2half(acc[d]);
}

// ================= host orchestration =================
extern "C" void kernel_launch(void* const* d_in, const int* in_sizes, int n_in,
                              void* d_out, int out_size) {
    const int*   idx    = (const int*)  d_in[0];
    const float* tok    = (const float*)d_in[1];
    const float* pos    = (const float*)d_in[2];
    const float* ln1_g  = (const float*)d_in[3];
    const float* ln1_b  = (const float*)d_in[4];
    const float* wq     = (const float*)d_in[5];
    const float* wk     = (const float*)d_in[6];
    const float* wv     = (const float*)d_in[7];
    const float* proj_w = (const float*)d_in[8];
    const float* proj_b = (const float*)d_in[9];
    const float* ln2_g  = (const float*)d_in[10];
    const float* ln2_b  = (const float*)d_in[11];
    const float* w1     = (const float*)d_in[12];
    const float* b1     = (const float*)d_in[13];
    const float* w2     = (const float*)d_in[14];
    const float* b2     = (const float*)d_in[15];
    const float* lnf_g  = (const float*)d_in[16];
    const float* lnf_b  = (const float*)d_in[17];
    const float* lm_w   = (const float*)d_in[18];
    const float* lm_b   = (const float*)d_in[19];
    float* out = (float*)d_out;

    float *x, *qkv;
    __half *a2, *ff, *bqkv, *bp, *bw1, *bw2, *blm;
    cudaGetSymbolAddress((void**)&x,    g_x);
    cudaGetSymbolAddress((void**)&qkv,  g_qkv);
    cudaGetSymbolAddress((void**)&a2,   g_act2);
    cudaGetSymbolAddress((void**)&ff,   g_ff);
    cudaGetSymbolAddress((void**)&bqkv, g_bqkv);
    cudaGetSymbolAddress((void**)&bp,   g_bp);
    cudaGetSymbolAddress((void**)&bw1,  g_bw1);
    cudaGetSymbolAddress((void**)&bw2,  g_bw2);
    cudaGetSymbolAddress((void**)&blm,  g_blm);

    cudaFuncSetAttribute(gemm_tc, cudaFuncAttributeMaxDynamicSharedMemorySize, GEMM_SMEM);
    const int attn_smem = ATTN_SMEM_FLOATS * (int)sizeof(float);
    cudaFuncSetAttribute(attn_kernel, cudaFuncAttributeMaxDynamicSharedMemorySize, attn_smem);

    dim3 wbk(32, 8);
    dim3 lnb(256, 2);
    const size_t LQKV = (size_t)QS * KLN;
    dim3 gQ (QS   / 128, MROWS / 128);      // (6, 128)
    dim3 gC (Cc   / 128, MROWS / 128);      // (2, 128)
    dim3 gF (DFFz / 128, MROWS / 128);      // (8, 128)
    dim3 gV (VPAD / 128, MROWS / 128);      // (79, 128)

    // launch 0: fused qkv weight split; 1: embed; 2: ln1(l=0); 3: QKV gemm(l=0)
    // (with harness's hidden launches, ncu -s 5 should land on the QKV GEMM)
    wsplit_qkv_kernel<<<dim3(Cc/32, Cc/32, 3*Ll), wbk>>>(wq, wk, wv, bqkv);
    embed_kernel<<<MROWS, Cc>>>(idx, tok, pos, x);
    ln_split2_kernel<<<MROWS/2, lnb>>>(x, ln1_g, ln1_b, a2);
    gemm_tc<<<gQ, 256, GEMM_SMEM>>>(a2, bqkv, nullptr, nullptr, qkv, nullptr, KLN, QS, 0);
    // remaining weight preps
    wsplit_f16_kernel<<<dim3(Cc/32, Cc/32, Ll), wbk>>>(proj_w, bp, Cc, Cc, (size_t)Cc*Cc, 0);
    wsplit_f16_kernel<<<dim3(DFFz/32, Cc/32, Ll), wbk>>>(w1, bw1, Cc, DFFz, (size_t)DFFz*KLN, 1);
    wsplit_f16_kernel<<<dim3(Cc/32, DFFz/32, Ll), wbk>>>(w2, bw2, DFFz, Cc, (size_t)Cc*DFFz, 0);
    wsplit_f16_kernel<<<dim3(VPAD/32, Cc/32, 1),  wbk>>>(lm_w, blm, Cc, Vv, 0, 0);

    for (int l = 0; l < Ll; l++) {
        if (l > 0) {
            ln_split2_kernel<<<MROWS/2, lnb>>>(x, ln1_g + (size_t)l*Cc, ln1_b + (size_t)l*Cc, a2);
            gemm_tc<<<gQ, 256, GEMM_SMEM>>>(a2, bqkv + (size_t)l*LQKV, nullptr, nullptr,
                                            qkv, nullptr, KLN, QS, 0);
        }
        attn_kernel<<<Bb*Hh, 128, attn_smem>>>(qkv, a2);   // single fp16 [M,256]
        gemm_tc<<<gC, 256, GEMM_SMEM>>>(a2, bp + (size_t)l*Cc*Cc, proj_b + (size_t)l*Cc,
                                        x, x, nullptr, Cc, Cc, 0);
        ln_split2_kernel<<<MROWS/2, lnb>>>(x, ln2_g + (size_t)l*Cc, ln2_b + (size_t)l*Cc, a2);
        gemm_tc<<<gF, 256, GEMM_SMEM>>>(a2, bw1 + (size_t)l*DFFz*KLN, b1 + (size_t)l*DFFz,
                                        nullptr, nullptr, ff, KLN, DFFz, 1);
        gemm_tc<<<gC, 256, GEMM_SMEM>>>(ff, bw2 + (size_t)l*Cc*DFFz, b2 + (size_t)l*Cc,
                                        x, x, nullptr, DFFz, Cc, 0);
    }

    ln_single_kernel<<<MROWS/2, lnb>>>(x, lnf_g, lnf_b, a2);
    gemm_tc<<<gV, 256, GEMM_SMEM>>>(a2, blm, lm_b, nullptr, out, nullptr, Cc, Vv, 0);
}

// round 15
// speedup vs baseline: 1.6488x; 1.0090x over previous
#include <cuda_runtime.h>
#include <cuda_bf16.h>
#include <cuda_fp16.h>
#include <cstdint>
#include <cstddef>

#define Bb   128
#define Tt   128
#define Cc   256
#define Hh   4
#define HSz  64
#define Ll   6
#define Vv   10000
#define DFFz 1024
#define MROWS (Bb*Tt)   // 16384
#define VPAD 10112      // ceil(10000/128)*128
#define QS   (3*Cc)     // fused qkv row stride (768)
#define KLN  (2*Cc)     // 512: 2-term fp16 acts (LN outputs -> QKV, FF1)

// ================= scratch (device globals) =================
__device__ __align__(256) float g_x  [MROWS * Cc];
__device__ __align__(256) float g_qkv[MROWS * QS];
__device__ __align__(256) __half g_act2[MROWS * KLN];         // LN 2-term [M,512] / single [M,256]
__device__ __align__(256) __half g_ff  [MROWS * DFFz];        // ff acts single fp16 [M, 1024]
__device__ __align__(256) __half g_bqkv[Ll * QS   * KLN];     // dup [768, 512] per layer
__device__ __align__(256) __half g_bp  [Ll * Cc   * Cc];      // single [256, 256]
__device__ __align__(256) __half g_bw1 [Ll * DFFz * KLN];     // dup [1024, 512]
__device__ __align__(256) __half g_bw2 [Ll * Cc   * DFFz];    // single [256, 1024]
__device__ __align__(256) __half g_blm [VPAD * Cc];           // single [10112, 256]

// ================= PTX helpers (arch-agnostic, valid on sm_103) =====
__device__ __forceinline__ uint32_t smem_u32(const void* p) {
    uint32_t a;
    asm("{ .reg .u64 t; cvta.to.shared.u64 t, %1; cvt.u32.u64 %0, t; }" : "=r"(a) : "l"(p));
    return a;
}
__device__ __forceinline__ void cp_async16(uint32_t saddr, const void* gaddr) {
    asm volatile("cp.async.cg.shared.global [%0], [%1], 16;" :: "r"(saddr), "l"(gaddr));
}
__device__ __forceinline__ void cp_commit() { asm volatile("cp.async.commit_group;" ::: "memory"); }
template <int N>
__device__ __forceinline__ void cp_wait() { asm volatile("cp.async.wait_group %0;" :: "n"(N) : "memory"); }

__device__ __forceinline__ void ldm_x4(uint32_t& r0, uint32_t& r1, uint32_t& r2, uint32_t& r3,
                                       uint32_t addr) {
    asm volatile("ldmatrix.sync.aligned.m8n8.x4.shared.b16 {%0,%1,%2,%3}, [%4];"
                 : "=r"(r0), "=r"(r1), "=r"(r2), "=r"(r3) : "r"(addr));
}
__device__ __forceinline__ void mma_f16(float* d, const uint32_t* a, const uint32_t* b) {
    asm volatile("mma.sync.aligned.m16n8k16.row.col.f32.f16.f16.f32 "
                 "{%0,%1,%2,%3}, {%4,%5,%6,%7}, {%8,%9}, {%0,%1,%2,%3};"
                 : "+f"(d[0]), "+f"(d[1]), "+f"(d[2]), "+f"(d[3])
                 : "r"(a[0]), "r"(a[1]), "r"(a[2]), "r"(a[3]), "r"(b[0]), "r"(b[1]));
}

// ================= embedding =================
__global__ void embed_kernel(const int* __restrict__ idx, const float* __restrict__ tok,
                             const float* __restrict__ pos, float* __restrict__ x) {
    int bt = blockIdx.x;
    int t  = bt % Tt;
    int tokid = idx[bt];
    int c = threadIdx.x;
    x[(size_t)bt * Cc + c] = tok[(size_t)tokid * Cc + c] + pos[(size_t)t * Cc + c];
}

// ================= LN core =================
__device__ __forceinline__ float ln_value(const float* __restrict__ x,
                                          const float* __restrict__ gam,
                                          const float* __restrict__ bet,
                                          int row, int tid, int ly) {
    float v = x[(size_t)row * Cc + tid];
    float s = v, sq = v * v;
    #pragma unroll
    for (int o = 16; o > 0; o >>= 1) {
        s  += __shfl_xor_sync(0xFFFFFFFFu, s,  o);
        sq += __shfl_xor_sync(0xFFFFFFFFu, sq, o);
    }
    __shared__ float ws[2][8], wsq[2][8];
    if ((tid & 31) == 0) { ws[ly][tid >> 5] = s; wsq[ly][tid >> 5] = sq; }
    __syncthreads();
    float S = 0.f, Q = 0.f;
    #pragma unroll
    for (int i = 0; i < 8; i++) { S += ws[ly][i]; Q += wsq[ly][i]; }
    float mean = S * (1.0f / Cc);
    float var  = Q * (1.0f / Cc) - mean * mean;
    float inv  = rsqrtf(var + 1e-5f);
    return (v - mean) * inv * gam[tid] + bet[tid];
}

// LN -> 2-term fp16 [M, 512] (exact acts), 2 rows/block
__global__ void ln_split2_kernel(const float* __restrict__ x, const float* __restrict__ gam,
                                 const float* __restrict__ bet, __half* __restrict__ out2) {
    int row = blockIdx.x * 2 + threadIdx.y;
    int tid = threadIdx.x;
    float y = ln_value(x, gam, bet, row, tid, threadIdx.y);
    __half hi = __float2half(y);
    __half lo = __float2half(y - __half2float(hi));
    size_t o = (size_t)row * KLN;
    out2[o + tid]      = hi;
    out2[o + Cc + tid] = lo;
}

// LN -> single fp16 [M, 256], 2 rows/block (head input)
__global__ void ln_single_kernel(const float* __restrict__ x, const float* __restrict__ gam,
                                 const float* __restrict__ bet, __half* __restrict__ out1) {
    int row = blockIdx.x * 2 + threadIdx.y;
    int tid = threadIdx.x;
    float y = ln_value(x, gam, bet, row, tid, threadIdx.y);
    out1[(size_t)row * Cc + tid] = __float2half(y);
}

// ================= weight transpose fp16: W[K,N] -> out[n, (1+dup)K] ======
__global__ void wsplit_f16_kernel(const float* __restrict__ W, __half* __restrict__ out,
                                  int K, int N, size_t lstride, int dup) {
    int l = blockIdx.z;
    W   += (size_t)l * K * N;
    out += (size_t)l * lstride;
    __shared__ float tile[32][33];
    int k0 = blockIdx.y * 32, n0 = blockIdx.x * 32;
    int tx = threadIdx.x, ty = threadIdx.y;   // 32 x 8
    #pragma unroll
    for (int i = 0; i < 32; i += 8) {
        int k = k0 + ty + i, n = n0 + tx;
        tile[ty + i][tx] = (n < N) ? W[(size_t)k * N + n] : 0.f;
    }
    __syncthreads();
    int rstride = (dup ? 2 : 1) * K;
    #pragma unroll
    for (int i = 0; i < 32; i += 8) {
        int n = n0 + ty + i, k = k0 + tx;
        __half h = __float2half(tile[tx][ty + i]);
        size_t rb = (size_t)n * rstride;
        out[rb + k] = h;
        if (dup) out[rb + K + k] = h;
    }
}

// fused qkv weight split: one launch, z = 3*Ll; which = z%3 picks wq/wk/wv
__global__ void wsplit_qkv_kernel(const float* __restrict__ Wq, const float* __restrict__ Wk,
                                  const float* __restrict__ Wv, __half* __restrict__ out) {
    int which = blockIdx.z % 3;
    int l     = blockIdx.z / 3;
    const float* W = (which == 0) ? Wq : (which == 1) ? Wk : Wv;
    W   += (size_t)l * Cc * Cc;
    out += (size_t)l * QS * KLN + (size_t)which * Cc * KLN;
    __shared__ float tile[32][33];
    int k0 = blockIdx.y * 32, n0 = blockIdx.x * 32;
    int tx = threadIdx.x, ty = threadIdx.y;
    #pragma unroll
    for (int i = 0; i < 32; i += 8) {
        int k = k0 + ty + i, n = n0 + tx;
        tile[ty + i][tx] = W[(size_t)k * Cc + n];
    }
    __syncthreads();
    #pragma unroll
    for (int i = 0; i < 32; i += 8) {
        int n = n0 + ty + i, k = k0 + tx;
        __half h = __float2half(tile[tx][ty + i]);
        size_t rb = (size_t)n * KLN;
        out[rb + k]      = h;
        out[rb + Cc + k] = h;
    }
}

// ================= HMMA fp16 GEMM, 128x128 tile, 3-stage cp.async, 2 CTAs/SM ====
#define LDA 72
#define CHELE (128 * LDA)
#define STAGE (2 * CHELE)
#define GEMM_SMEM (3 * STAGE * 2)          // 110592 bytes
#define LDE 132                            // f32 epilogue stride: 528B rows, 16B-aligned

__global__ void __launch_bounds__(256, 2)
gemm_tc(const __half* __restrict__ A2, const __half* __restrict__ B2,
        const float* __restrict__ bias, const float* __restrict__ Rres,
        float* __restrict__ D32, __half* __restrict__ D2,
        int Kfull, int N, int relu) {
    extern __shared__ char smem_raw[];
    uint32_t sb = smem_u32(smem_raw);
    int tid = threadIdx.x, lane = tid & 31, wid = tid >> 5;
    int wm = wid & 3, wn = wid >> 2;       // 4Mx2N warps, warp tile 32x64
    int bx = blockIdx.x, by = blockIdx.y;

    const __half* Abase = A2 + (size_t)(by * 128) * Kfull;
    const __half* Bbase = B2 + (size_t)(bx * 128) * Kfull;
    int nch = Kfull >> 6;

    float acc[2][8][4];
    #pragma unroll
    for (int mt = 0; mt < 2; mt++)
        #pragma unroll
        for (int nt = 0; nt < 8; nt++)
            #pragma unroll
            for (int i = 0; i < 4; i++) acc[mt][nt][i] = 0.f;

    int lrow[4], lunit[4];
    #pragma unroll
    for (int j = 0; j < 4; j++) {
        int lin = tid + j * 256;
        lrow[j]  = lin >> 3;
        lunit[j] = (lin & 7) << 3;
    }

    auto issue_load = [&](int kc, int buf) {
        const __half* Ag = Abase + kc * 64;
        const __half* Bg = Bbase + kc * 64;
        uint32_t sA = sb + (uint32_t)(buf * STAGE) * 2;
        uint32_t sB = sA + (uint32_t)CHELE * 2;
        #pragma unroll
        for (int j = 0; j < 4; j++) {
            cp_async16(sA + (uint32_t)(lrow[j] * LDA + lunit[j]) * 2,
                       Ag + (size_t)lrow[j] * Kfull + lunit[j]);
            cp_async16(sB + (uint32_t)(lrow[j] * LDA + lunit[j]) * 2,
                       Bg + (size_t)lrow[j] * Kfull + lunit[j]);
        }
        cp_commit();
    };

    issue_load(0, 0);
    if (nch > 1) issue_load(1, 1);

    int a_row = wm * 32 + (lane & 15);
    int a_kc  = (lane >> 4) * 8;
    int b_row = wn * 64 + (lane & 7) + ((lane >> 4) << 3);
    int b_kc  = (lane & 8);

    for (int kc = 0; kc < nch; kc++) {
        if (kc + 1 < nch) cp_wait<1>(); else cp_wait<0>();
        __syncthreads();
        if (kc + 2 < nch) issue_load(kc + 2, (kc + 2) % 3);

        int buf = kc % 3;
        uint32_t sA = sb + (uint32_t)(buf * STAGE) * 2;
        uint32_t sB = sA + (uint32_t)CHELE * 2;

        #pragma unroll
        for (int ks = 0; ks < 4; ks++) {
            uint32_t a[2][4], b[8][2];
            #pragma unroll
            for (int mt = 0; mt < 2; mt++) {
                uint32_t addr = sA + (uint32_t)((a_row + mt * 16) * LDA + ks * 16 + a_kc) * 2;
                ldm_x4(a[mt][0], a[mt][1], a[mt][2], a[mt][3], addr);
            }
            #pragma unroll
            for (int ntp = 0; ntp < 4; ntp++) {
                uint32_t addr = sB + (uint32_t)((b_row + ntp * 16) * LDA + ks * 16 + b_kc) * 2;
                ldm_x4(b[ntp*2][0], b[ntp*2][1], b[ntp*2+1][0], b[ntp*2+1][1], addr);
            }
            #pragma unroll
            for (int mt = 0; mt < 2; mt++)
                #pragma unroll
                for (int nt = 0; nt < 8; nt++)
                    mma_f16(acc[mt][nt], a[mt], b[nt]);
        }
    }

    // ---- epilogue: scatter acc -> smem, then fully-coalesced pass ----
    __syncthreads();
    float* st = (float*)smem_raw;          // 128 x LDE f32 tile (67584 B)
    int g = lane >> 2, tig = lane & 3;
    #pragma unroll
    for (int mt = 0; mt < 2; mt++) {
        #pragma unroll
        for (int nt = 0; nt < 8; nt++) {
            int c = wn * 64 + nt * 8 + 2 * tig;
            #pragma unroll
            for (int half = 0; half < 2; half++) {
                int r = wm * 32 + mt * 16 + g + half * 8;
                st[r * LDE + c]     = acc[mt][nt][half * 2 + 0];
                st[r * LDE + c + 1] = acc[mt][nt][half * 2 + 1];
            }
        }
    }
    __syncthreads();
    #pragma unroll
    for (int i = 0; i < 16; i++) {
        int pos = i * 1024 + tid * 4;
        int r = pos >> 7, c = pos & 127;
        int col = bx * 128 + c;
        if (col >= N) continue;
        int row = by * 128 + r;
        float4 v = *(float4*)&st[r * LDE + c];
        if (bias) {
            float4 bv = *(const float4*)&bias[col];
            v.x += bv.x; v.y += bv.y; v.z += bv.z; v.w += bv.w;
        }
        if (D32) {
            if (Rres) {
                float4 rv = *(const float4*)&Rres[(size_t)row * N + col];
                v.x += rv.x; v.y += rv.y; v.z += rv.z; v.w += rv.w;
            }
            *(float4*)&D32[(size_t)row * N + col] = v;
        } else {
            if (relu) {
                v.x = fmaxf(v.x, 0.f); v.y = fmaxf(v.y, 0.f);
                v.z = fmaxf(v.z, 0.f); v.w = fmaxf(v.w, 0.f);
            }
            __half2* dp = (__half2*)&D2[(size_t)row * N + col];
            dp[0] = __floats2half2_rn(v.x, v.y);
            dp[1] = __floats2half2_rn(v.z, v.w);
        }
    }
}

// ======== fused causal attention, smem-BROADCAST inner loops, fp16 out ========
// All lanes of a warp walk the same j -> K/V row reads are smem broadcasts
// (conflict-degree 1 instead of 32). Causality via warp bound j <= (tid|31),
// predicated accumulate. Per-row arithmetic order identical to previous round.
#define ATTN_SMEM_FLOATS (Tt*HSz + Tt*129)
__global__ void attn_kernel(const float* __restrict__ qkv, __half* __restrict__ out1) {
    extern __shared__ char smem_raw[];
    float* smem = (float*)smem_raw;
    float* kv = smem;
    float* sc = smem + Tt * HSz;
    int b = blockIdx.x >> 2;
    int h = blockIdx.x & 3;
    int tid = threadIdx.x;
    int jmax = tid | 31;               // warp-uniform causal bound
    size_t base = (size_t)b * Tt * QS + (size_t)h * HSz;

    for (int i = tid; i < Tt * HSz; i += 128) {
        int r = i >> 6, d = i & 63;
        kv[i] = qkv[base + Cc + (size_t)r * QS + d];       // K
    }
    __syncthreads();

    float qr[HSz];
    #pragma unroll
    for (int d = 0; d < HSz; d += 4) {
        float4 t4 = *(const float4*)&qkv[base + (size_t)tid * QS + d];
        qr[d] = t4.x; qr[d+1] = t4.y; qr[d+2] = t4.z; qr[d+3] = t4.w;
    }

    const float scale = 0.0625f;   // C^-0.5 (matches reference)
    float* myrow = sc + tid * 129;
    float mx = -1e30f;
    for (int j = 0; j <= jmax; j++) {
        const float4* kj4 = (const float4*)(kv + j * HSz);  // broadcast within warp
        float s0 = 0.f, s1 = 0.f, s2 = 0.f, s3 = 0.f;
        #pragma unroll
        for (int d4 = 0; d4 < 16; d4++) {
            float4 t = kj4[d4];
            s0 += qr[d4*4+0] * t.x;
            s1 += qr[d4*4+1] * t.y;
            s2 += qr[d4*4+2] * t.z;
            s3 += qr[d4*4+3] * t.w;
        }
        float s = ((s0 + s1) + (s2 + s3)) * scale;
        if (j <= tid) { myrow[j] = s; mx = fmaxf(mx, s); }
    }
    float sum = 0.f;
    for (int j = 0; j <= tid; j++) {
        float e = __expf(myrow[j] - mx);
        myrow[j] = e;
        sum += e;
    }
    float inv = 1.0f / sum;

    __syncthreads();
    for (int i = tid; i < Tt * HSz; i += 128) {
        int r = i >> 6, d = i & 63;
        kv[i] = qkv[base + 2 * Cc + (size_t)r * QS + d];   // V
    }
    __syncthreads();

    float acc[HSz];
    #pragma unroll
    for (int d = 0; d < HSz; d++) acc[d] = 0.f;
    for (int j = 0; j <= jmax; j++) {
        float w = (j <= tid) ? myrow[j] * inv : 0.f;
        const float4* vj4 = (const float4*)(kv + j * HSz);  // broadcast within warp
        #pragma unroll
        for (int d4 = 0; d4 < 16; d4++) {
            float4 t = vj4[d4];
            acc[d4*4+0] += w * t.x;
            acc[d4*4+1] += w * t.y;
            acc[d4*4+2] += w * t.z;
            acc[d4*4+3] += w * t.w;
        }
    }
    int row = b * Tt + tid;
    size_t o = (size_t)row * Cc + h * HSz;
    #pragma unroll
    for (int d = 0; d < HSz; d++)
        out1[o + d] = __float2half(acc[d]);
}

// ================= host orchestration =================
extern "C" void kernel_launch(void* const* d_in, const int* in_sizes, int n_in,
                              void* d_out, int out_size) {
    const int*   idx    = (const int*)  d_in[0];
    const float* tok    = (const float*)d_in[1];
    const float* pos    = (const float*)d_in[2];
    const float* ln1_g  = (const float*)d_in[3];
    const float* ln1_b  = (const float*)d_in[4];
    const float* wq     = (const float*)d_in[5];
    const float* wk     = (const float*)d_in[6];
    const float* wv     = (const float*)d_in[7];
    const float* proj_w = (const float*)d_in[8];
    const float* proj_b = (const float*)d_in[9];
    const float* ln2_g  = (const float*)d_in[10];
    const float* ln2_b  = (const float*)d_in[11];
    const float* w1     = (const float*)d_in[12];
    const float* b1     = (const float*)d_in[13];
    const float* w2     = (const float*)d_in[14];
    const float* b2     = (const float*)d_in[15];
    const float* lnf_g  = (const float*)d_in[16];
    const float* lnf_b  = (const float*)d_in[17];
    const float* lm_w   = (const float*)d_in[18];
    const float* lm_b   = (const float*)d_in[19];
    float* out = (float*)d_out;

    float *x, *qkv;
    __half *a2, *ff, *bqkv, *bp, *bw1, *bw2, *blm;
    cudaGetSymbolAddress((void**)&x,    g_x);
    cudaGetSymbolAddress((void**)&qkv,  g_qkv);
    cudaGetSymbolAddress((void**)&a2,   g_act2);
    cudaGetSymbolAddress((void**)&ff,   g_ff);
    cudaGetSymbolAddress((void**)&bqkv, g_bqkv);
    cudaGetSymbolAddress((void**)&bp,   g_bp);
    cudaGetSymbolAddress((void**)&bw1,  g_bw1);
    cudaGetSymbolAddress((void**)&bw2,  g_bw2);
    cudaGetSymbolAddress((void**)&blm,  g_blm);

    cudaFuncSetAttribute(gemm_tc, cudaFuncAttributeMaxDynamicSharedMemorySize, GEMM_SMEM);
    const int attn_smem = ATTN_SMEM_FLOATS * (int)sizeof(float);
    cudaFuncSetAttribute(attn_kernel, cudaFuncAttributeMaxDynamicSharedMemorySize, attn_smem);

    dim3 wbk(32, 8);
    dim3 lnb(256, 2);
    const size_t LQKV = (size_t)QS * KLN;
    dim3 gQ (QS   / 128, MROWS / 128);      // (6, 128)
    dim3 gC (Cc   / 128, MROWS / 128);      // (2, 128)
    dim3 gF (DFFz / 128, MROWS / 128);      // (8, 128)
    dim3 gV (VPAD / 128, MROWS / 128);      // (79, 128)

    // launch 0: fused qkv weight split; 1: embed; 2: ln1(l=0); 3: QKV gemm(l=0)
    wsplit_qkv_kernel<<<dim3(Cc/32, Cc/32, 3*Ll), wbk>>>(wq, wk, wv, bqkv);
    embed_kernel<<<MROWS, Cc>>>(idx, tok, pos, x);
    ln_split2_kernel<<<MROWS/2, lnb>>>(x, ln1_g, ln1_b, a2);
    gemm_tc<<<gQ, 256, GEMM_SMEM>>>(a2, bqkv, nullptr, nullptr, qkv, nullptr, KLN, QS, 0);
    // remaining weight preps
    wsplit_f16_kernel<<<dim3(Cc/32, Cc/32, Ll), wbk>>>(proj_w, bp, Cc, Cc, (size_t)Cc*Cc, 0);
    wsplit_f16_kernel<<<dim3(DFFz/32, Cc/32, Ll), wbk>>>(w1, bw1, Cc, DFFz, (size_t)DFFz*KLN, 1);
    wsplit_f16_kernel<<<dim3(Cc/32, DFFz/32, Ll), wbk>>>(w2, bw2, DFFz, Cc, (size_t)Cc*DFFz, 0);
    wsplit_f16_kernel<<<dim3(VPAD/32, Cc/32, 1),  wbk>>>(lm_w, blm, Cc, Vv, 0, 0);

    for (int l = 0; l < Ll; l++) {
        if (l > 0) {
            ln_split2_kernel<<<MROWS/2, lnb>>>(x, ln1_g + (size_t)l*Cc, ln1_b + (size_t)l*Cc, a2);
            gemm_tc<<<gQ, 256, GEMM_SMEM>>>(a2, bqkv + (size_t)l*LQKV, nullptr, nullptr,
                                            qkv, nullptr, KLN, QS, 0);
        }
        attn_kernel<<<Bb*Hh, 128, attn_smem>>>(qkv, a2);   // single fp16 [M,256]
        gemm_tc<<<gC, 256, GEMM_SMEM>>>(a2, bp + (size_t)l*Cc*Cc, proj_b + (size_t)l*Cc,
                                        x, x, nullptr, Cc, Cc, 0);
        ln_split2_kernel<<<MROWS/2, lnb>>>(x, ln2_g + (size_t)l*Cc, ln2_b + (size_t)l*Cc, a2);
        gemm_tc<<<gF, 256, GEMM_SMEM>>>(a2, bw1 + (size_t)l*DFFz*KLN, b1 + (size_t)l*DFFz,
                                        nullptr, nullptr, ff, KLN, DFFz, 1);
        gemm_tc<<<gC, 256, GEMM_SMEM>>>(ff, bw2 + (size_t)l*Cc*DFFz, b2 + (size_t)l*Cc,
                                        x, x, nullptr, DFFz, Cc, 0);
    }

    ln_single_kernel<<<MROWS/2, lnb>>>(x, lnf_g, lnf_b, a2);
    gemm_tc<<<gV, 256, GEMM_SMEM>>>(a2, blm, lm_b, nullptr, out, nullptr, Cc, Vv, 0);
}

// round 16
// speedup vs baseline: 1.8802x; 1.1404x over previous
#include <cuda_runtime.h>
#include <cuda_bf16.h>
#include <cuda_fp16.h>
#include <cstdint>
#include <cstddef>

#define Bb   128
#define Tt   128
#define Cc   256
#define Hh   4
#define HSz  64
#define Ll   6
#define Vv   10000
#define DFFz 1024
#define MROWS (Bb*Tt)   // 16384
#define VPAD 10112      // ceil(10000/128)*128
#define QS   (3*Cc)     // fused qkv row stride (768)

// ================= scratch (device globals) =================
__device__ __align__(256) float g_x  [MROWS * Cc];
__device__ __align__(256) float g_qkv[MROWS * QS];
__device__ __align__(256) __half g_act [MROWS * Cc];          // single fp16 acts [M, 256]
__device__ __align__(256) __half g_ff  [MROWS * DFFz];        // ff acts single fp16 [M, 1024]
__device__ __align__(256) __half g_bqkv[Ll * QS   * Cc];      // [768, 256] per layer
__device__ __align__(256) __half g_bp  [Ll * Cc   * Cc];      // [256, 256]
__device__ __align__(256) __half g_bw1 [Ll * DFFz * Cc];      // [1024, 256]
__device__ __align__(256) __half g_bw2 [Ll * Cc   * DFFz];    // [256, 1024]
__device__ __align__(256) __half g_blm [VPAD * Cc];           // [10112, 256]

// ================= PTX helpers (arch-agnostic, valid on sm_103) =====
__device__ __forceinline__ uint32_t smem_u32(const void* p) {
    uint32_t a;
    asm("{ .reg .u64 t; cvta.to.shared.u64 t, %1; cvt.u32.u64 %0, t; }" : "=r"(a) : "l"(p));
    return a;
}
__device__ __forceinline__ void cp_async16(uint32_t saddr, const void* gaddr) {
    asm volatile("cp.async.cg.shared.global [%0], [%1], 16;" :: "r"(saddr), "l"(gaddr));
}
__device__ __forceinline__ void cp_commit() { asm volatile("cp.async.commit_group;" ::: "memory"); }
template <int N>
__device__ __forceinline__ void cp_wait() { asm volatile("cp.async.wait_group %0;" :: "n"(N) : "memory"); }

__device__ __forceinline__ void ldm_x4(uint32_t& r0, uint32_t& r1, uint32_t& r2, uint32_t& r3,
                                       uint32_t addr) {
    asm volatile("ldmatrix.sync.aligned.m8n8.x4.shared.b16 {%0,%1,%2,%3}, [%4];"
                 : "=r"(r0), "=r"(r1), "=r"(r2), "=r"(r3) : "r"(addr));
}
__device__ __forceinline__ void mma_f16(float* d, const uint32_t* a, const uint32_t* b) {
    asm volatile("mma.sync.aligned.m16n8k16.row.col.f32.f16.f16.f32 "
                 "{%0,%1,%2,%3}, {%4,%5,%6,%7}, {%8,%9}, {%0,%1,%2,%3};"
                 : "+f"(d[0]), "+f"(d[1]), "+f"(d[2]), "+f"(d[3])
                 : "r"(a[0]), "r"(a[1]), "r"(a[2]), "r"(a[3]), "r"(b[0]), "r"(b[1]));
}

// ================= embedding =================
__global__ void embed_kernel(const int* __restrict__ idx, const float* __restrict__ tok,
                             const float* __restrict__ pos, float* __restrict__ x) {
    int bt = blockIdx.x;
    int t  = bt % Tt;
    int tokid = idx[bt];
    int c = threadIdx.x;
    x[(size_t)bt * Cc + c] = tok[(size_t)tokid * Cc + c] + pos[(size_t)t * Cc + c];
}

// ================= LN -> single fp16 [M, 256], 2 rows/block =================
__global__ void ln_single_kernel(const float* __restrict__ x, const float* __restrict__ gam,
                                 const float* __restrict__ bet, __half* __restrict__ out1) {
    int row = blockIdx.x * 2 + threadIdx.y;
    int tid = threadIdx.x;
    int ly  = threadIdx.y;
    float v = x[(size_t)row * Cc + tid];
    float s = v, sq = v * v;
    #pragma unroll
    for (int o = 16; o > 0; o >>= 1) {
        s  += __shfl_xor_sync(0xFFFFFFFFu, s,  o);
        sq += __shfl_xor_sync(0xFFFFFFFFu, sq, o);
    }
    __shared__ float ws[2][8], wsq[2][8];
    if ((tid & 31) == 0) { ws[ly][tid >> 5] = s; wsq[ly][tid >> 5] = sq; }
    __syncthreads();
    float S = 0.f, Q = 0.f;
    #pragma unroll
    for (int i = 0; i < 8; i++) { S += ws[ly][i]; Q += wsq[ly][i]; }
    float mean = S * (1.0f / Cc);
    float var  = Q * (1.0f / Cc) - mean * mean;
    float inv  = rsqrtf(var + 1e-5f);
    float y = (v - mean) * inv * gam[tid] + bet[tid];
    out1[(size_t)row * Cc + tid] = __float2half(y);
}

// ================= weight transpose fp16: W[K,N] -> out[n, K] ======
__global__ void wsplit_f16_kernel(const float* __restrict__ W, __half* __restrict__ out,
                                  int K, int N, size_t lstride) {
    int l = blockIdx.z;
    W   += (size_t)l * K * N;
    out += (size_t)l * lstride;
    __shared__ float tile[32][33];
    int k0 = blockIdx.y * 32, n0 = blockIdx.x * 32;
    int tx = threadIdx.x, ty = threadIdx.y;   // 32 x 8
    #pragma unroll
    for (int i = 0; i < 32; i += 8) {
        int k = k0 + ty + i, n = n0 + tx;
        tile[ty + i][tx] = (n < N) ? W[(size_t)k * N + n] : 0.f;
    }
    __syncthreads();
    #pragma unroll
    for (int i = 0; i < 32; i += 8) {
        int n = n0 + ty + i, k = k0 + tx;
        out[(size_t)n * K + k] = __float2half(tile[tx][ty + i]);
    }
}

// fused qkv weight split: one launch, z = 3*Ll; which = z%3 picks wq/wk/wv
__global__ void wsplit_qkv_kernel(const float* __restrict__ Wq, const float* __restrict__ Wk,
                                  const float* __restrict__ Wv, __half* __restrict__ out) {
    int which = blockIdx.z % 3;
    int l     = blockIdx.z / 3;
    const float* W = (which == 0) ? Wq : (which == 1) ? Wk : Wv;
    W   += (size_t)l * Cc * Cc;
    out += (size_t)l * QS * Cc + (size_t)which * Cc * Cc;
    __shared__ float tile[32][33];
    int k0 = blockIdx.y * 32, n0 = blockIdx.x * 32;
    int tx = threadIdx.x, ty = threadIdx.y;
    #pragma unroll
    for (int i = 0; i < 32; i += 8) {
        int k = k0 + ty + i, n = n0 + tx;
        tile[ty + i][tx] = W[(size_t)k * Cc + n];
    }
    __syncthreads();
    #pragma unroll
    for (int i = 0; i < 32; i += 8) {
        int n = n0 + ty + i, k = k0 + tx;
        out[(size_t)n * Cc + k] = __float2half(tile[tx][ty + i]);
    }
}

// ================= HMMA fp16 GEMM, 128x128 tile, 3-stage cp.async, 2 CTAs/SM ====
#define LDA 72
#define CHELE (128 * LDA)
#define STAGE (2 * CHELE)
#define GEMM_SMEM (3 * STAGE * 2)          // 110592 bytes
#define LDE 132                            // f32 epilogue stride: 528B rows, 16B-aligned

__global__ void __launch_bounds__(256, 2)
gemm_tc(const __half* __restrict__ A2, const __half* __restrict__ B2,
        const float* __restrict__ bias, const float* __restrict__ Rres,
        float* __restrict__ D32, __half* __restrict__ D2,
        int Kfull, int N, int relu) {
    extern __shared__ char smem_raw[];
    uint32_t sb = smem_u32(smem_raw);
    int tid = threadIdx.x, lane = tid & 31, wid = tid >> 5;
    int wm = wid & 3, wn = wid >> 2;       // 4Mx2N warps, warp tile 32x64
    int bx = blockIdx.x, by = blockIdx.y;

    const __half* Abase = A2 + (size_t)(by * 128) * Kfull;
    const __half* Bbase = B2 + (size_t)(bx * 128) * Kfull;
    int nch = Kfull >> 6;

    float acc[2][8][4];
    #pragma unroll
    for (int mt = 0; mt < 2; mt++)
        #pragma unroll
        for (int nt = 0; nt < 8; nt++)
            #pragma unroll
            for (int i = 0; i < 4; i++) acc[mt][nt][i] = 0.f;

    int lrow[4], lunit[4];
    #pragma unroll
    for (int j = 0; j < 4; j++) {
        int lin = tid + j * 256;
        lrow[j]  = lin >> 3;
        lunit[j] = (lin & 7) << 3;
    }

    auto issue_load = [&](int kc, int buf) {
        const __half* Ag = Abase + kc * 64;
        const __half* Bg = Bbase + kc * 64;
        uint32_t sA = sb + (uint32_t)(buf * STAGE) * 2;
        uint32_t sB = sA + (uint32_t)CHELE * 2;
        #pragma unroll
        for (int j = 0; j < 4; j++) {
            cp_async16(sA + (uint32_t)(lrow[j] * LDA + lunit[j]) * 2,
                       Ag + (size_t)lrow[j] * Kfull + lunit[j]);
            cp_async16(sB + (uint32_t)(lrow[j] * LDA + lunit[j]) * 2,
                       Bg + (size_t)lrow[j] * Kfull + lunit[j]);
        }
        cp_commit();
    };

    issue_load(0, 0);
    if (nch > 1) issue_load(1, 1);

    int a_row = wm * 32 + (lane & 15);
    int a_kc  = (lane >> 4) * 8;
    int b_row = wn * 64 + (lane & 7) + ((lane >> 4) << 3);
    int b_kc  = (lane & 8);

    for (int kc = 0; kc < nch; kc++) {
        if (kc + 1 < nch) cp_wait<1>(); else cp_wait<0>();
        __syncthreads();
        if (kc + 2 < nch) issue_load(kc + 2, (kc + 2) % 3);

        int buf = kc % 3;
        uint32_t sA = sb + (uint32_t)(buf * STAGE) * 2;
        uint32_t sB = sA + (uint32_t)CHELE * 2;

        #pragma unroll
        for (int ks = 0; ks < 4; ks++) {
            uint32_t a[2][4], b[8][2];
            #pragma unroll
            for (int mt = 0; mt < 2; mt++) {
                uint32_t addr = sA + (uint32_t)((a_row + mt * 16) * LDA + ks * 16 + a_kc) * 2;
                ldm_x4(a[mt][0], a[mt][1], a[mt][2], a[mt][3], addr);
            }
            #pragma unroll
            for (int ntp = 0; ntp < 4; ntp++) {
                uint32_t addr = sB + (uint32_t)((b_row + ntp * 16) * LDA + ks * 16 + b_kc) * 2;
                ldm_x4(b[ntp*2][0], b[ntp*2][1], b[ntp*2+1][0], b[ntp*2+1][1], addr);
            }
            #pragma unroll
            for (int mt = 0; mt < 2; mt++)
                #pragma unroll
                for (int nt = 0; nt < 8; nt++)
                    mma_f16(acc[mt][nt], a[mt], b[nt]);
        }
    }

    // ---- epilogue: scatter acc -> smem, then fully-coalesced pass ----
    __syncthreads();
    float* st = (float*)smem_raw;          // 128 x LDE f32 tile (67584 B)
    int g = lane >> 2, tig = lane & 3;
    #pragma unroll
    for (int mt = 0; mt < 2; mt++) {
        #pragma unroll
        for (int nt = 0; nt < 8; nt++) {
            int c = wn * 64 + nt * 8 + 2 * tig;
            #pragma unroll
            for (int half = 0; half < 2; half++) {
                int r = wm * 32 + mt * 16 + g + half * 8;
                st[r * LDE + c]     = acc[mt][nt][half * 2 + 0];
                st[r * LDE + c + 1] = acc[mt][nt][half * 2 + 1];
            }
        }
    }
    __syncthreads();
    #pragma unroll
    for (int i = 0; i < 16; i++) {
        int pos = i * 1024 + tid * 4;
        int r = pos >> 7, c = pos & 127;
        int col = bx * 128 + c;
        if (col >= N) continue;
        int row = by * 128 + r;
        float4 v = *(float4*)&st[r * LDE + c];
        if (bias) {
            float4 bv = *(const float4*)&bias[col];
            v.x += bv.x; v.y += bv.y; v.z += bv.z; v.w += bv.w;
        }
        if (D32) {
            if (Rres) {
                float4 rv = *(const float4*)&Rres[(size_t)row * N + col];
                v.x += rv.x; v.y += rv.y; v.z += rv.z; v.w += rv.w;
            }
            *(float4*)&D32[(size_t)row * N + col] = v;
        } else {
            if (relu) {
                v.x = fmaxf(v.x, 0.f); v.y = fmaxf(v.y, 0.f);
                v.z = fmaxf(v.z, 0.f); v.w = fmaxf(v.w, 0.f);
            }
            __half2* dp = (__half2*)&D2[(size_t)row * N + col];
            dp[0] = __floats2half2_rn(v.x, v.y);
            dp[1] = __floats2half2_rn(v.z, v.w);
        }
    }
}

// ======== fused causal attention, smem-broadcast inner loops, fp16 out ========
#define ATTN_SMEM_FLOATS (Tt*HSz + Tt*129)
__global__ void attn_kernel(const float* __restrict__ qkv, __half* __restrict__ out1) {
    extern __shared__ char smem_raw[];
    float* smem = (float*)smem_raw;
    float* kv = smem;
    float* sc = smem + Tt * HSz;
    int b = blockIdx.x >> 2;
    int h = blockIdx.x & 3;
    int tid = threadIdx.x;
    int jmax = tid | 31;               // warp-uniform causal bound
    size_t base = (size_t)b * Tt * QS + (size_t)h * HSz;

    for (int i = tid; i < Tt * HSz; i += 128) {
        int r = i >> 6, d = i & 63;
        kv[i] = qkv[base + Cc + (size_t)r * QS + d];       // K
    }
    __syncthreads();

    float qr[HSz];
    #pragma unroll
    for (int d = 0; d < HSz; d += 4) {
        float4 t4 = *(const float4*)&qkv[base + (size_t)tid * QS + d];
        qr[d] = t4.x; qr[d+1] = t4.y; qr[d+2] = t4.z; qr[d+3] = t4.w;
    }

    const float scale = 0.0625f;   // C^-0.5 (matches reference)
    float* myrow = sc + tid * 129;
    float mx = -1e30f;
    for (int j = 0; j <= jmax; j++) {
        const float4* kj4 = (const float4*)(kv + j * HSz);
        float s0 = 0.f, s1 = 0.f, s2 = 0.f, s3 = 0.f;
        #pragma unroll
        for (int d4 = 0; d4 < 16; d4++) {
            float4 t = kj4[d4];
            s0 += qr[d4*4+0] * t.x;
            s1 += qr[d4*4+1] * t.y;
            s2 += qr[d4*4+2] * t.z;
            s3 += qr[d4*4+3] * t.w;
        }
        float s = ((s0 + s1) + (s2 + s3)) * scale;
        if (j <= tid) { myrow[j] = s; mx = fmaxf(mx, s); }
    }
    float sum = 0.f;
    for (int j = 0; j <= tid; j++) {
        float e = __expf(myrow[j] - mx);
        myrow[j] = e;
        sum += e;
    }
    float inv = 1.0f / sum;

    __syncthreads();
    for (int i = tid; i < Tt * HSz; i += 128) {
        int r = i >> 6, d = i & 63;
        kv[i] = qkv[base + 2 * Cc + (size_t)r * QS + d];   // V
    }
    __syncthreads();

    float acc[HSz];
    #pragma unroll
    for (int d = 0; d < HSz; d++) acc[d] = 0.f;
    for (int j = 0; j <= jmax; j++) {
        float w = (j <= tid) ? myrow[j] * inv : 0.f;
        const float4* vj4 = (const float4*)(kv + j * HSz);
        #pragma unroll
        for (int d4 = 0; d4 < 16; d4++) {
            float4 t = vj4[d4];
            acc[d4*4+0] += w * t.x;
            acc[d4*4+1] += w * t.y;
            acc[d4*4+2] += w * t.z;
            acc[d4*4+3] += w * t.w;
        }
    }
    int row = b * Tt + tid;
    size_t o = (size_t)row * Cc + h * HSz;
    #pragma unroll
    for (int d = 0; d < HSz; d++)
        out1[o + d] = __float2half(acc[d]);
}

// ================= host orchestration =================
extern "C" void kernel_launch(void* const* d_in, const int* in_sizes, int n_in,
                              void* d_out, int out_size) {
    const int*   idx    = (const int*)  d_in[0];
    const float* tok    = (const float*)d_in[1];
    const float* pos    = (const float*)d_in[2];
    const float* ln1_g  = (const float*)d_in[3];
    const float* ln1_b  = (const float*)d_in[4];
    const float* wq     = (const float*)d_in[5];
    const float* wk     = (const float*)d_in[6];
    const float* wv     = (const float*)d_in[7];
    const float* proj_w = (const float*)d_in[8];
    const float* proj_b = (const float*)d_in[9];
    const float* ln2_g  = (const float*)d_in[10];
    const float* ln2_b  = (const float*)d_in[11];
    const float* w1     = (const float*)d_in[12];
    const float* b1     = (const float*)d_in[13];
    const float* w2     = (const float*)d_in[14];
    const float* b2     = (const float*)d_in[15];
    const float* lnf_g  = (const float*)d_in[16];
    const float* lnf_b  = (const float*)d_in[17];
    const float* lm_w   = (const float*)d_in[18];
    const float* lm_b   = (const float*)d_in[19];
    float* out = (float*)d_out;

    float *x, *qkv;
    __half *a1, *ff, *bqkv, *bp, *bw1, *bw2, *blm;
    cudaGetSymbolAddress((void**)&x,    g_x);
    cudaGetSymbolAddress((void**)&qkv,  g_qkv);
    cudaGetSymbolAddress((void**)&a1,   g_act);
    cudaGetSymbolAddress((void**)&ff,   g_ff);
    cudaGetSymbolAddress((void**)&bqkv, g_bqkv);
    cudaGetSymbolAddress((void**)&bp,   g_bp);
    cudaGetSymbolAddress((void**)&bw1,  g_bw1);
    cudaGetSymbolAddress((void**)&bw2,  g_bw2);
    cudaGetSymbolAddress((void**)&blm,  g_blm);

    cudaFuncSetAttribute(gemm_tc, cudaFuncAttributeMaxDynamicSharedMemorySize, GEMM_SMEM);
    const int attn_smem = ATTN_SMEM_FLOATS * (int)sizeof(float);
    cudaFuncSetAttribute(attn_kernel, cudaFuncAttributeMaxDynamicSharedMemorySize, attn_smem);

    dim3 wbk(32, 8);
    dim3 lnb(256, 2);
    const size_t LQKV = (size_t)QS * Cc;    // per-layer stride of fused qkv weight
    dim3 gQ (QS   / 128, MROWS / 128);      // (6, 128)
    dim3 gC (Cc   / 128, MROWS / 128);      // (2, 128)
    dim3 gF (DFFz / 128, MROWS / 128);      // (8, 128)
    dim3 gV (VPAD / 128, MROWS / 128);      // (79, 128)

    // launch 0: fused qkv weight split; 1: embed; 2: ln1(l=0); 3: QKV gemm(l=0)
    wsplit_qkv_kernel<<<dim3(Cc/32, Cc/32, 3*Ll), wbk>>>(wq, wk, wv, bqkv);
    embed_kernel<<<MROWS, Cc>>>(idx, tok, pos, x);
    ln_single_kernel<<<MROWS/2, lnb>>>(x, ln1_g, ln1_b, a1);
    gemm_tc<<<gQ, 256, GEMM_SMEM>>>(a1, bqkv, nullptr, nullptr, qkv, nullptr, Cc, QS, 0);
    // remaining weight preps
    wsplit_f16_kernel<<<dim3(Cc/32, Cc/32, Ll), wbk>>>(proj_w, bp, Cc, Cc, (size_t)Cc*Cc);
    wsplit_f16_kernel<<<dim3(DFFz/32, Cc/32, Ll), wbk>>>(w1, bw1, Cc, DFFz, (size_t)DFFz*Cc);
    wsplit_f16_kernel<<<dim3(Cc/32, DFFz/32, Ll), wbk>>>(w2, bw2, DFFz, Cc, (size_t)Cc*DFFz);
    wsplit_f16_kernel<<<dim3(VPAD/32, Cc/32, 1),  wbk>>>(lm_w, blm, Cc, Vv, 0);

    for (int l = 0; l < Ll; l++) {
        if (l > 0) {
            ln_single_kernel<<<MROWS/2, lnb>>>(x, ln1_g + (size_t)l*Cc, ln1_b + (size_t)l*Cc, a1);
            gemm_tc<<<gQ, 256, GEMM_SMEM>>>(a1, bqkv + (size_t)l*LQKV, nullptr, nullptr,
                                            qkv, nullptr, Cc, QS, 0);
        }
        attn_kernel<<<Bb*Hh, 128, attn_smem>>>(qkv, a1);   // single fp16 [M,256]
        gemm_tc<<<gC, 256, GEMM_SMEM>>>(a1, bp + (size_t)l*Cc*Cc, proj_b + (size_t)l*Cc,
                                        x, x, nullptr, Cc, Cc, 0);
        ln_single_kernel<<<MROWS/2, lnb>>>(x, ln2_g + (size_t)l*Cc, ln2_b + (size_t)l*Cc, a1);
        gemm_tc<<<gF, 256, GEMM_SMEM>>>(a1, bw1 + (size_t)l*DFFz*Cc, b1 + (size_t)l*DFFz,
                                        nullptr, nullptr, ff, Cc, DFFz, 1);
        gemm_tc<<<gC, 256, GEMM_SMEM>>>(ff, bw2 + (size_t)l*Cc*DFFz, b2 + (size_t)l*Cc,
                                        x, x, nullptr, DFFz, Cc, 0);
    }

    ln_single_kernel<<<MROWS/2, lnb>>>(x, lnf_g, lnf_b, a1);
    gemm_tc<<<gV, 256, GEMM_SMEM>>>(a1, blm, lm_b, nullptr, out, nullptr, Cc, Vv, 0);
}